// round 1
// baseline (speedup 1.0000x reference)
#include <cuda_runtime.h>
#include <cstdint>
#include <cstddef>

#define N_NODES 1024
#define C_DIM   2048
#define KNB     8
#define KC      8
#define N_EDGES (N_NODES + KC)

// Select JAX threefry flavor for jax.random.permutation(key(42), 1024).
// 1 = partitionable (default in modern JAX), 0 = legacy/original path.
#ifndef JAX_PARTITIONABLE
#define JAX_PARTITIONABLE 1
#endif

typedef unsigned long long u64;

// ---------------- scratch (static __device__, no runtime allocation) ----------
__device__ float g_xf[N_NODES * C_DIM];
__device__ float g_sq[N_NODES];
__device__ float g_D[N_NODES * N_NODES];
__device__ int   g_neigh[N_NODES * KNB];
__device__ int   g_perm[N_NODES];
__device__ int   g_assign[N_NODES];
__device__ float g_E[N_EDGES * C_DIM];
__device__ float g_X1[N_EDGES * C_DIM];
__device__ float g_Y[N_NODES * C_DIM];

// ---------------- threefry-2x32 (20 rounds), matches JAX ---------------------
__device__ __forceinline__ void threefry2x32(unsigned k0, unsigned k1,
                                             unsigned& x0, unsigned& x1) {
    unsigned ks2 = k0 ^ k1 ^ 0x1BD11BDAu;
    x0 += k0; x1 += k1;
#define TF_R(r) { x0 += x1; x1 = (x1 << (r)) | (x1 >> (32 - (r))); x1 ^= x0; }
    TF_R(13) TF_R(15) TF_R(26) TF_R(6)
    x0 += k1;  x1 += ks2 + 1u;
    TF_R(17) TF_R(29) TF_R(16) TF_R(24)
    x0 += ks2; x1 += k0 + 2u;
    TF_R(13) TF_R(15) TF_R(26) TF_R(6)
    x0 += k0;  x1 += k1 + 3u;
    TF_R(17) TF_R(29) TF_R(16) TF_R(24)
    x0 += k1;  x1 += ks2 + 4u;
    TF_R(13) TF_R(15) TF_R(26) TF_R(6)
    x0 += ks2; x1 += k0 + 5u;
#undef TF_R
}

// perm = jax.random.permutation(jax.random.key(42), 1024)
// _shuffle: 1 round; key,subkey = split(key); bits = random_bits(subkey, 32, (1024,))
// then stable ascending sort_key_val(bits, arange).
__global__ void perm_kernel(int* __restrict__ perm) {
    __shared__ u64 keys[N_NODES];
    int tid = threadIdx.x;
    unsigned s0, s1;
#if JAX_PARTITIONABLE
    // split: new_key[i] = cipher(key, hi=0, lo=i); subkey = new_key[1]
    { unsigned a0 = 0u, a1 = 1u; threefry2x32(0u, 42u, a0, a1); s0 = a0; s1 = a1; }
#else
    // split: out = cipher over iota(4) split in halves; subkey = (out[2], out[3])
    { unsigned a0 = 0u, a1 = 2u; threefry2x32(0u, 42u, a0, a1);
      unsigned b0 = 1u, b1 = 3u; threefry2x32(0u, 42u, b0, b1);
      s0 = a1; s1 = b1; }
#endif
    if (tid < 512) {
#if JAX_PARTITIONABLE
        // bits[i] = o0 ^ o1 of cipher(subkey, hi=0, lo=i)
        unsigned x0 = 0u, x1 = (unsigned)tid;
        threefry2x32(s0, s1, x0, x1);
        keys[tid] = ((u64)(x0 ^ x1) << 32) | (unsigned)tid;
        unsigned y0 = 0u, y1 = (unsigned)(tid + 512);
        threefry2x32(s0, s1, y0, y1);
        keys[tid + 512] = ((u64)(y0 ^ y1) << 32) | (unsigned)(tid + 512);
#else
        // bits[i] = cipher(sub, i, i+512).o0 ; bits[i+512] = .o1
        unsigned x0 = (unsigned)tid, x1 = (unsigned)(tid + 512);
        threefry2x32(s0, s1, x0, x1);
        keys[tid]       = ((u64)x0 << 32) | (unsigned)tid;
        keys[tid + 512] = ((u64)x1 << 32) | (unsigned)(tid + 512);
#endif
    }
    __syncthreads();
    // bitonic sort of 1024 u64 keys (stable via index in low 32 bits)
    for (int k = 2; k <= N_NODES; k <<= 1) {
        for (int j = k >> 1; j > 0; j >>= 1) {
            int ixj = tid ^ j;
            if (ixj > tid) {
                u64 a = keys[tid], b = keys[ixj];
                bool up = ((tid & k) == 0);
                if ((a > b) == up) { keys[tid] = b; keys[ixj] = a; }
            }
            __syncthreads();
        }
    }
    perm[tid] = (int)(keys[tid] & 0xffffffffull);
}

// ---------------- fp32 tiled GEMM: C[M,N] = A[M,K] @ B[K,N] (+bias) ----------
__global__ void sgemm_kernel(const float* __restrict__ A, const float* __restrict__ B,
                             const float* __restrict__ bias, float* __restrict__ C,
                             int M, int N, int K) {
    __shared__ float As[16][64];
    __shared__ float Bs[16][64];
    const int tid  = threadIdx.x;
    const int row0 = blockIdx.y * 64;
    const int col0 = blockIdx.x * 64;
    const int arow = tid >> 2,  acol = (tid & 3) << 2;
    const int brow = tid >> 4,  bcol = (tid & 15) << 2;
    const int ty = tid >> 4, tx = tid & 15;
    float acc[4][4] = {};
    for (int k0 = 0; k0 < K; k0 += 16) {
        float4 av = make_float4(0.f, 0.f, 0.f, 0.f);
        if (row0 + arow < M)
            av = *(const float4*)(A + (size_t)(row0 + arow) * K + k0 + acol);
        As[acol + 0][arow] = av.x; As[acol + 1][arow] = av.y;
        As[acol + 2][arow] = av.z; As[acol + 3][arow] = av.w;
        *(float4*)(&Bs[brow][bcol]) =
            *(const float4*)(B + (size_t)(k0 + brow) * N + col0 + bcol);
        __syncthreads();
#pragma unroll
        for (int k = 0; k < 16; k++) {
            float4 a = *(const float4*)(&As[k][ty << 2]);
            float4 b = *(const float4*)(&Bs[k][tx << 2]);
            acc[0][0] += a.x * b.x; acc[0][1] += a.x * b.y; acc[0][2] += a.x * b.z; acc[0][3] += a.x * b.w;
            acc[1][0] += a.y * b.x; acc[1][1] += a.y * b.y; acc[1][2] += a.y * b.z; acc[1][3] += a.y * b.w;
            acc[2][0] += a.z * b.x; acc[2][1] += a.z * b.y; acc[2][2] += a.z * b.z; acc[2][3] += a.z * b.w;
            acc[3][0] += a.w * b.x; acc[3][1] += a.w * b.y; acc[3][2] += a.w * b.z; acc[3][3] += a.w * b.w;
        }
        __syncthreads();
    }
#pragma unroll
    for (int i = 0; i < 4; i++) {
        int r = row0 + (ty << 2) + i;
        if (r < M) {
#pragma unroll
            for (int j = 0; j < 4; j++) {
                int c = col0 + (tx << 2) + j;
                float v = acc[i][j];
                if (bias) v += bias[c];
                C[(size_t)r * N + c] = v;
            }
        }
    }
}

// ---------------- row squared norms -----------------------------------------
__global__ void rowsq_kernel(const float* __restrict__ xf, float* __restrict__ sq) {
    int row = blockIdx.x, tid = threadIdx.x;
    const float* x = xf + (size_t)row * C_DIM;
    float s = 0.f;
    for (int c = tid; c < C_DIM; c += 256) { float v = x[c]; s = fmaf(v, v, s); }
    for (int off = 16; off; off >>= 1) s += __shfl_xor_sync(0xffffffffu, s, off);
    __shared__ float r[8];
    if ((tid & 31) == 0) r[tid >> 5] = s;
    __syncthreads();
    if (tid == 0) { float t = 0.f; for (int w = 0; w < 8; w++) t += r[w]; sq[row] = t; }
}

// ---------------- pairwise distance: D = sqrt(max(sq_i+sq_j-2*x_i.x_j, 0)) ---
__global__ void dist_kernel(const float* __restrict__ xf, const float* __restrict__ sq,
                            float* __restrict__ D) {
    __shared__ float As[16][64];
    __shared__ float Bs[16][64];
    const int tid  = threadIdx.x;
    const int row0 = blockIdx.y * 64;
    const int col0 = blockIdx.x * 64;
    const int lrow = tid >> 2, lcol = (tid & 3) << 2;
    const int ty = tid >> 4, tx = tid & 15;
    float acc[4][4] = {};
    for (int k0 = 0; k0 < C_DIM; k0 += 16) {
        float4 av = *(const float4*)(xf + (size_t)(row0 + lrow) * C_DIM + k0 + lcol);
        As[lcol + 0][lrow] = av.x; As[lcol + 1][lrow] = av.y;
        As[lcol + 2][lrow] = av.z; As[lcol + 3][lrow] = av.w;
        float4 bv = *(const float4*)(xf + (size_t)(col0 + lrow) * C_DIM + k0 + lcol);
        Bs[lcol + 0][lrow] = bv.x; Bs[lcol + 1][lrow] = bv.y;
        Bs[lcol + 2][lrow] = bv.z; Bs[lcol + 3][lrow] = bv.w;
        __syncthreads();
#pragma unroll
        for (int k = 0; k < 16; k++) {
            float4 a = *(const float4*)(&As[k][ty << 2]);
            float4 b = *(const float4*)(&Bs[k][tx << 2]);
            acc[0][0] += a.x * b.x; acc[0][1] += a.x * b.y; acc[0][2] += a.x * b.z; acc[0][3] += a.x * b.w;
            acc[1][0] += a.y * b.x; acc[1][1] += a.y * b.y; acc[1][2] += a.y * b.z; acc[1][3] += a.y * b.w;
            acc[2][0] += a.z * b.x; acc[2][1] += a.z * b.y; acc[2][2] += a.z * b.z; acc[2][3] += a.z * b.w;
            acc[3][0] += a.w * b.x; acc[3][1] += a.w * b.y; acc[3][2] += a.w * b.z; acc[3][3] += a.w * b.w;
        }
        __syncthreads();
    }
#pragma unroll
    for (int i = 0; i < 4; i++) {
        int r = row0 + (ty << 2) + i;
        float sqr = sq[r];
#pragma unroll
        for (int j = 0; j < 4; j++) {
            int c = col0 + (tx << 2) + j;
            float d2 = sqr + sq[c] - 2.f * acc[i][j];
            D[(size_t)r * N_NODES + c] = sqrtf(fmaxf(d2, 0.f));
        }
    }
}

// ---------------- kNN: 8 smallest distances per row (diag excluded) ----------
__global__ void knn_kernel(const float* __restrict__ D, int* __restrict__ neigh) {
    int gw = (blockIdx.x * blockDim.x + threadIdx.x) >> 5;
    int lane = threadIdx.x & 31;
    if (gw >= N_NODES) return;
    const float* row = D + (size_t)gw * N_NODES;
    float val[8]; int idx[8];
#pragma unroll
    for (int r = 0; r < 8; r++) { val[r] = __int_as_float(0x7f800000); idx[r] = 0; }
    for (int j = lane; j < N_NODES; j += 32) {
        if (j == gw) continue;
        float v = row[j];
        if (v < val[7]) {
            val[7] = v; idx[7] = j;
#pragma unroll
            for (int p = 7; p > 0; p--) {
                if (val[p] < val[p - 1]) {
                    float tv = val[p]; val[p] = val[p - 1]; val[p - 1] = tv;
                    int   ti = idx[p]; idx[p] = idx[p - 1]; idx[p - 1] = ti;
                }
            }
        }
    }
    // merge: 8 rounds of warp argmin over each lane's current head
    int ptr = 0;
    for (int r = 0; r < 8; r++) {
        u64 key = ~0ull;
        if (ptr < 8)
            key = ((u64)__float_as_uint(val[ptr]) << 32) | (unsigned)idx[ptr];
        u64 m = key;
        for (int off = 16; off; off >>= 1) {
            u64 o = __shfl_xor_sync(0xffffffffu, m, off);
            if (o < m) m = o;
        }
        if (lane == 0) neigh[gw * KNB + r] = (int)(m & 0xffffffffull);
        if (key == m) ptr++;
    }
}

// ---------------- sequential k-means scan (1 block, 256 threads) -------------
__global__ void kmeans_kernel(const float* __restrict__ D, const int* __restrict__ perm,
                              int* __restrict__ assign_out) {
    __shared__ float S[KC][N_NODES];   // per-cluster running dist sums
    __shared__ int   a[N_NODES];
    __shared__ int   cent[KC];
    __shared__ int   cnt[KC];
    __shared__ u64   red[8];
    __shared__ int   cur_c;
    const int tid = threadIdx.x, lane = tid & 31, wid = tid >> 5;
    const float INF = __int_as_float(0x7f800000);

    for (int i = tid; i < N_NODES; i += 256) a[i] = -1;
    __syncthreads();
    if (tid < KC) { a[perm[tid]] = tid; cent[tid] = perm[tid]; cnt[tid] = 1; }
    __syncthreads();
    for (int c = 0; c < KC; c++) {
        int pc = cent[c];
        for (int i = tid; i < N_NODES; i += 256) S[c][i] = D[(size_t)pc * N_NODES + i];
    }
    __syncthreads();

    for (int step = 0; step < N_NODES - KC; step++) {
        const int ni = perm[KC + step];
        const float* Drow = D + (size_t)ni * N_NODES;
        if (wid == 0) {
            float v = (lane < KC) ? Drow[cent[lane]] : INF;
            u64 key = ((u64)__float_as_uint(v) << 32) | (unsigned)lane;
            for (int off = 4; off; off >>= 1) {
                u64 o = __shfl_xor_sync(0xffffffffu, key, off);
                if (o < key) key = o;
            }
            if (lane == 0) {
                int c = (int)(key & 0xffffffffull);
                cur_c = c; cnt[c] += 1;
            }
        }
        __syncthreads();
        const int c = cur_c;
        const float denom = (float)(cnt[c] - 1);
        u64 best = ~0ull;
#pragma unroll
        for (int w = 0; w < 4; w++) {
            int i = tid + w * 256;
            float s = S[c][i] + Drow[i];
            S[c][i] = s;
            bool memb = (a[i] == c) | (i == ni);
            float v = memb ? (s / denom) : INF;
            u64 key = ((u64)__float_as_uint(v) << 32) | (unsigned)i;
            if (key < best) best = key;
        }
        for (int off = 16; off; off >>= 1) {
            u64 o = __shfl_xor_sync(0xffffffffu, best, off);
            if (o < best) best = o;
        }
        if (lane == 0) red[wid] = best;
        __syncthreads();
        if (tid == 0) {
            u64 m = red[0];
            for (int w = 1; w < 8; w++) if (red[w] < m) m = red[w];
            cent[c] = (int)(m & 0xffffffffull);
            a[ni] = c;
        }
        __syncthreads();
    }
    for (int i = tid; i < N_NODES; i += 256) assign_out[i] = a[i];
}

// ---------------- E[e] = sum_{v in neigh(e)} xf[v]  (local hyperedges) -------
__global__ void agg_local_kernel(const float* __restrict__ xf, const int* __restrict__ neigh,
                                 float* __restrict__ E) {
    int e = blockIdx.x;
    int nb[KNB];
#pragma unroll
    for (int j = 0; j < KNB; j++) nb[j] = neigh[e * KNB + j];
    for (int c = threadIdx.x; c < C_DIM; c += 256) {
        float s = 0.f;
#pragma unroll
        for (int j = 0; j < KNB; j++) s += xf[(size_t)nb[j] * C_DIM + c];
        E[(size_t)e * C_DIM + c] = s;
    }
}

// ---------------- E[n+c] = sum_{assign[v]==c} xf[v] --------------------------
__global__ void agg_global_kernel(const float* __restrict__ xf, const int* __restrict__ assign_,
                                  float* __restrict__ E) {
    __shared__ int sa[N_NODES];
    int tid = threadIdx.x;
    for (int i = tid; i < N_NODES; i += 256) sa[i] = assign_[i];
    __syncthreads();
    int c = blockIdx.x;
    int col = blockIdx.y * 256 + tid;
    float s = 0.f;
    for (int i = 0; i < N_NODES; i++)
        if (sa[i] == c) s += xf[(size_t)i * C_DIM + col];
    E[(size_t)(N_NODES + c) * C_DIM + col] = s;
}

// ---------------- Y[v] = sum_{e: v in neigh(e)} X1[e] + X1[n+assign[v]] ------
__global__ void agg_out_kernel(const float* __restrict__ X1, const int* __restrict__ neigh,
                               const int* __restrict__ assign_, float* __restrict__ Y) {
    int v = blockIdx.x;
    __shared__ int list[N_NODES];
    __shared__ int cnt_s;
    int tid = threadIdx.x, lane = tid & 31, wid = tid >> 5;
    if (wid == 0) {
        int cnt = 0;
        for (int base = 0; base < N_NODES; base += 32) {
            int e = base + lane;
            const int4* p = (const int4*)(neigh + e * KNB);
            int4 q0 = p[0], q1 = p[1];
            bool m = (q0.x == v) | (q0.y == v) | (q0.z == v) | (q0.w == v) |
                     (q1.x == v) | (q1.y == v) | (q1.z == v) | (q1.w == v);
            unsigned msk = __ballot_sync(0xffffffffu, m);
            if (m) list[cnt + __popc(msk & ((1u << lane) - 1u))] = e;
            cnt += __popc(msk);
        }
        if (lane == 0) cnt_s = cnt;
    }
    __syncthreads();
    int cnt = cnt_s;
    int ge = N_NODES + assign_[v];
    float s[8];
#pragma unroll
    for (int w = 0; w < 8; w++) s[w] = X1[(size_t)ge * C_DIM + tid + w * 256];
    for (int t = 0; t < cnt; t++) {
        const float* xr = X1 + (size_t)list[t] * C_DIM;
#pragma unroll
        for (int w = 0; w < 8; w++) s[w] += xr[tid + w * 256];
    }
#pragma unroll
    for (int w = 0; w < 8; w++) Y[(size_t)v * C_DIM + tid + w * 256] = s[w];
}

// ---------------- host launcher ----------------------------------------------
extern "C" void kernel_launch(void* const* d_in, const int* in_sizes, int n_in,
                              void* d_out, int out_size) {
    const float* x0  = (const float*)d_in[0];
    const float* wfc = (const float*)d_in[1];
    const float* bfc = (const float*)d_in[2];
    const float* w1  = (const float*)d_in[3];
    const float* w2  = (const float*)d_in[4];
    float* out = (float*)d_out;

    float *xf, *sq, *D, *E, *X1, *Y;
    int *neigh, *perm, *assign_;
    cudaGetSymbolAddress((void**)&xf,      g_xf);
    cudaGetSymbolAddress((void**)&sq,      g_sq);
    cudaGetSymbolAddress((void**)&D,       g_D);
    cudaGetSymbolAddress((void**)&neigh,   g_neigh);
    cudaGetSymbolAddress((void**)&perm,    g_perm);
    cudaGetSymbolAddress((void**)&assign_, g_assign);
    cudaGetSymbolAddress((void**)&E,       g_E);
    cudaGetSymbolAddress((void**)&X1,      g_X1);
    cudaGetSymbolAddress((void**)&Y,       g_Y);

    perm_kernel<<<1, 1024>>>(perm);
    sgemm_kernel<<<dim3(C_DIM / 64, N_NODES / 64), 256>>>(x0, wfc, bfc, xf,
                                                          N_NODES, C_DIM, C_DIM);
    rowsq_kernel<<<N_NODES, 256>>>(xf, sq);
    dist_kernel<<<dim3(N_NODES / 64, N_NODES / 64), 256>>>(xf, sq, D);
    knn_kernel<<<N_NODES / 8, 256>>>(D, neigh);
    kmeans_kernel<<<1, 256>>>(D, perm, assign_);
    agg_local_kernel<<<N_NODES, 256>>>(xf, neigh, E);
    agg_global_kernel<<<dim3(KC, C_DIM / 256), 256>>>(xf, assign_, E);
    sgemm_kernel<<<dim3(C_DIM / 64, (N_EDGES + 63) / 64), 256>>>(E, w1, nullptr, X1,
                                                                 N_EDGES, C_DIM, C_DIM);
    agg_out_kernel<<<N_NODES, 256>>>(X1, neigh, assign_, Y);
    sgemm_kernel<<<dim3(C_DIM / 64, N_NODES / 64), 256>>>(Y, w2, nullptr, out,
                                                          N_NODES, C_DIM, C_DIM);
}

// round 2
// speedup vs baseline: 1.1181x; 1.1181x over previous
#include <cuda_runtime.h>
#include <cstdint>
#include <cstddef>

#define N_NODES 1024
#define C_DIM   2048
#define KNB     8
#define KC      8
#define N_EDGES (N_NODES + KC)
#define NSTEPS  (N_NODES - KC)

typedef unsigned long long u64;

// ---------------- scratch (static __device__, no runtime allocation) ----------
__device__ float g_xf[N_NODES * C_DIM];
__device__ float g_sq[N_NODES];
__device__ float g_D[N_NODES * N_NODES];
__device__ int   g_neigh[N_NODES * KNB];
__device__ int   g_perm[N_NODES];
__device__ int   g_assign[N_NODES];
__device__ float g_E[N_EDGES * C_DIM];
__device__ float g_X1[N_EDGES * C_DIM];
__device__ float g_Y[N_NODES * C_DIM];

// ---------------- threefry-2x32 (20 rounds), matches JAX ---------------------
__device__ __forceinline__ void threefry2x32(unsigned k0, unsigned k1,
                                             unsigned& x0, unsigned& x1) {
    unsigned ks2 = k0 ^ k1 ^ 0x1BD11BDAu;
    x0 += k0; x1 += k1;
#define TF_R(r) { x0 += x1; x1 = (x1 << (r)) | (x1 >> (32 - (r))); x1 ^= x0; }
    TF_R(13) TF_R(15) TF_R(26) TF_R(6)
    x0 += k1;  x1 += ks2 + 1u;
    TF_R(17) TF_R(29) TF_R(16) TF_R(24)
    x0 += ks2; x1 += k0 + 2u;
    TF_R(13) TF_R(15) TF_R(26) TF_R(6)
    x0 += k0;  x1 += k1 + 3u;
    TF_R(17) TF_R(29) TF_R(16) TF_R(24)
    x0 += k1;  x1 += ks2 + 4u;
    TF_R(13) TF_R(15) TF_R(26) TF_R(6)
    x0 += ks2; x1 += k0 + 5u;
#undef TF_R
}

// perm = jax.random.permutation(jax.random.key(42), 1024)  [partitionable path]
__global__ void perm_kernel(int* __restrict__ perm) {
    __shared__ u64 keys[N_NODES];
    int tid = threadIdx.x;
    unsigned s0, s1;
    { unsigned a0 = 0u, a1 = 1u; threefry2x32(0u, 42u, a0, a1); s0 = a0; s1 = a1; }
    if (tid < 512) {
        unsigned x0 = 0u, x1 = (unsigned)tid;
        threefry2x32(s0, s1, x0, x1);
        keys[tid] = ((u64)(x0 ^ x1) << 32) | (unsigned)tid;
        unsigned y0 = 0u, y1 = (unsigned)(tid + 512);
        threefry2x32(s0, s1, y0, y1);
        keys[tid + 512] = ((u64)(y0 ^ y1) << 32) | (unsigned)(tid + 512);
    }
    __syncthreads();
    for (int k = 2; k <= N_NODES; k <<= 1) {
        for (int j = k >> 1; j > 0; j >>= 1) {
            int ixj = tid ^ j;
            if (ixj > tid) {
                u64 a = keys[tid], b = keys[ixj];
                bool up = ((tid & k) == 0);
                if ((a > b) == up) { keys[tid] = b; keys[ixj] = a; }
            }
            __syncthreads();
        }
    }
    perm[tid] = (int)(keys[tid] & 0xffffffffull);
}

// ---------------- fp32 SGEMM: 128x128 tile, 8x8/thread, reg double-buffer ----
__global__ __launch_bounds__(256) void sgemm_kernel(
    const float* __restrict__ A, const float* __restrict__ B,
    const float* __restrict__ bias, float* __restrict__ C,
    int M, int N, int K) {
    __shared__ float As[16][128];
    __shared__ float Bs[16][128];
    const int tid  = threadIdx.x;
    const int row0 = blockIdx.y * 128;
    const int col0 = blockIdx.x * 128;
    const int am = tid >> 2, ak = (tid & 3) << 2;   // A rows am, am+64
    const int bk = tid >> 5, bn = (tid & 31) << 2;  // B k-rows bk, bk+8
    const int ty = tid >> 4, tx = tid & 15;
    const float4 z4 = make_float4(0.f, 0.f, 0.f, 0.f);

    float4 a0, a1, b0, b1;
    {
        int r = row0 + am;
        a0 = (r      < M) ? *(const float4*)(A + (size_t)r        * K + ak) : z4;
        a1 = (r + 64 < M) ? *(const float4*)(A + (size_t)(r + 64) * K + ak) : z4;
        b0 = *(const float4*)(B + (size_t)bk       * N + col0 + bn);
        b1 = *(const float4*)(B + (size_t)(bk + 8) * N + col0 + bn);
    }
    float acc[8][8] = {};

#define STORE_TILES()                                                         \
    {                                                                         \
        As[ak + 0][am] = a0.x; As[ak + 1][am] = a0.y;                         \
        As[ak + 2][am] = a0.z; As[ak + 3][am] = a0.w;                         \
        As[ak + 0][am + 64] = a1.x; As[ak + 1][am + 64] = a1.y;               \
        As[ak + 2][am + 64] = a1.z; As[ak + 3][am + 64] = a1.w;               \
        *(float4*)&Bs[bk][bn]     = b0;                                       \
        *(float4*)&Bs[bk + 8][bn] = b1;                                       \
    }
#define COMPUTE_TILE()                                                        \
    _Pragma("unroll")                                                         \
    for (int kt = 0; kt < 16; kt++) {                                         \
        float af[8], bf[8];                                                   \
        *(float4*)&af[0] = *(const float4*)&As[kt][ty * 8];                   \
        *(float4*)&af[4] = *(const float4*)&As[kt][ty * 8 + 4];               \
        *(float4*)&bf[0] = *(const float4*)&Bs[kt][tx * 8];                   \
        *(float4*)&bf[4] = *(const float4*)&Bs[kt][tx * 8 + 4];               \
        _Pragma("unroll")                                                     \
        for (int i = 0; i < 8; i++)                                           \
            _Pragma("unroll")                                                 \
            for (int j = 0; j < 8; j++)                                       \
                acc[i][j] = fmaf(af[i], bf[j], acc[i][j]);                    \
    }

    STORE_TILES();
    __syncthreads();
    for (int k0 = 16; k0 < K; k0 += 16) {
        int r = row0 + am;
        a0 = (r      < M) ? *(const float4*)(A + (size_t)r        * K + k0 + ak) : z4;
        a1 = (r + 64 < M) ? *(const float4*)(A + (size_t)(r + 64) * K + k0 + ak) : z4;
        b0 = *(const float4*)(B + (size_t)(k0 + bk)     * N + col0 + bn);
        b1 = *(const float4*)(B + (size_t)(k0 + bk + 8) * N + col0 + bn);
        COMPUTE_TILE();
        __syncthreads();
        STORE_TILES();
        __syncthreads();
    }
    COMPUTE_TILE();

    float4 bias0 = z4, bias1 = z4;
    if (bias) {
        bias0 = *(const float4*)(bias + col0 + tx * 8);
        bias1 = *(const float4*)(bias + col0 + tx * 8 + 4);
    }
#pragma unroll
    for (int i = 0; i < 8; i++) {
        int r = row0 + ty * 8 + i;
        if (r < M) {
            float4 o0 = make_float4(acc[i][0] + bias0.x, acc[i][1] + bias0.y,
                                    acc[i][2] + bias0.z, acc[i][3] + bias0.w);
            float4 o1 = make_float4(acc[i][4] + bias1.x, acc[i][5] + bias1.y,
                                    acc[i][6] + bias1.z, acc[i][7] + bias1.w);
            *(float4*)(C + (size_t)r * N + col0 + tx * 8)     = o0;
            *(float4*)(C + (size_t)r * N + col0 + tx * 8 + 4) = o1;
        }
    }
#undef STORE_TILES
#undef COMPUTE_TILE
}

// ---------------- row squared norms -----------------------------------------
__global__ void rowsq_kernel(const float* __restrict__ xf, float* __restrict__ sq) {
    int row = blockIdx.x, tid = threadIdx.x;
    const float* x = xf + (size_t)row * C_DIM;
    float s = 0.f;
    for (int c = tid; c < C_DIM; c += 256) { float v = x[c]; s = fmaf(v, v, s); }
    for (int off = 16; off; off >>= 1) s += __shfl_xor_sync(0xffffffffu, s, off);
    __shared__ float r[8];
    if ((tid & 31) == 0) r[tid >> 5] = s;
    __syncthreads();
    if (tid == 0) { float t = 0.f; for (int w = 0; w < 8; w++) t += r[w]; sq[row] = t; }
}

// ---------------- pairwise distance: 128x64 tile, 8x4/thread -----------------
__global__ __launch_bounds__(256) void dist_kernel(
    const float* __restrict__ xf, const float* __restrict__ sq,
    float* __restrict__ D) {
    __shared__ float As[16][128];
    __shared__ float Bs[16][64];
    const int tid  = threadIdx.x;
    const int row0 = blockIdx.y * 128;
    const int col0 = blockIdx.x * 64;
    const int am = tid >> 2, ak = (tid & 3) << 2;
    const int ty = tid >> 4, tx = tid & 15;

    float4 a0, a1, b0;
    {
        a0 = *(const float4*)(xf + (size_t)(row0 + am)      * C_DIM + ak);
        a1 = *(const float4*)(xf + (size_t)(row0 + am + 64) * C_DIM + ak);
        b0 = *(const float4*)(xf + (size_t)(col0 + am)      * C_DIM + ak);
    }
    float acc[8][4] = {};

#define D_STORE()                                                             \
    {                                                                         \
        As[ak + 0][am] = a0.x; As[ak + 1][am] = a0.y;                         \
        As[ak + 2][am] = a0.z; As[ak + 3][am] = a0.w;                         \
        As[ak + 0][am + 64] = a1.x; As[ak + 1][am + 64] = a1.y;               \
        As[ak + 2][am + 64] = a1.z; As[ak + 3][am + 64] = a1.w;               \
        if (am < 64) {                                                        \
            Bs[ak + 0][am] = b0.x; Bs[ak + 1][am] = b0.y;                     \
            Bs[ak + 2][am] = b0.z; Bs[ak + 3][am] = b0.w;                     \
        }                                                                     \
    }
#define D_COMPUTE()                                                           \
    _Pragma("unroll")                                                         \
    for (int kt = 0; kt < 16; kt++) {                                         \
        float af[8], bf[4];                                                   \
        *(float4*)&af[0] = *(const float4*)&As[kt][ty * 8];                   \
        *(float4*)&af[4] = *(const float4*)&As[kt][ty * 8 + 4];               \
        *(float4*)&bf[0] = *(const float4*)&Bs[kt][tx * 4];                   \
        _Pragma("unroll")                                                     \
        for (int i = 0; i < 8; i++)                                           \
            _Pragma("unroll")                                                 \
            for (int j = 0; j < 4; j++)                                       \
                acc[i][j] = fmaf(af[i], bf[j], acc[i][j]);                    \
    }

    D_STORE();
    __syncthreads();
    for (int k0 = 16; k0 < C_DIM; k0 += 16) {
        a0 = *(const float4*)(xf + (size_t)(row0 + am)      * C_DIM + k0 + ak);
        a1 = *(const float4*)(xf + (size_t)(row0 + am + 64) * C_DIM + k0 + ak);
        b0 = *(const float4*)(xf + (size_t)(col0 + am)      * C_DIM + k0 + ak);
        D_COMPUTE();
        __syncthreads();
        D_STORE();
        __syncthreads();
    }
    D_COMPUTE();

#pragma unroll
    for (int i = 0; i < 8; i++) {
        int r = row0 + ty * 8 + i;
        float sqr = sq[r];
        float4 o;
        int c = col0 + tx * 4;
        o.x = sqrtf(fmaxf(sqr + sq[c + 0] - 2.f * acc[i][0], 0.f));
        o.y = sqrtf(fmaxf(sqr + sq[c + 1] - 2.f * acc[i][1], 0.f));
        o.z = sqrtf(fmaxf(sqr + sq[c + 2] - 2.f * acc[i][2], 0.f));
        o.w = sqrtf(fmaxf(sqr + sq[c + 3] - 2.f * acc[i][3], 0.f));
        *(float4*)(D + (size_t)r * N_NODES + c) = o;
    }
#undef D_STORE
#undef D_COMPUTE
}

// ---------------- kNN: 8 smallest per row (diag excluded) --------------------
__global__ void knn_kernel(const float* __restrict__ D, int* __restrict__ neigh) {
    int gw = (blockIdx.x * blockDim.x + threadIdx.x) >> 5;
    int lane = threadIdx.x & 31;
    if (gw >= N_NODES) return;
    const float* row = D + (size_t)gw * N_NODES;
    float val[8]; int idx[8];
#pragma unroll
    for (int r = 0; r < 8; r++) { val[r] = __int_as_float(0x7f800000); idx[r] = 0; }
    for (int j = lane; j < N_NODES; j += 32) {
        if (j == gw) continue;
        float v = row[j];
        if (v < val[7]) {
            val[7] = v; idx[7] = j;
#pragma unroll
            for (int p = 7; p > 0; p--) {
                if (val[p] < val[p - 1]) {
                    float tv = val[p]; val[p] = val[p - 1]; val[p - 1] = tv;
                    int   ti = idx[p]; idx[p] = idx[p - 1]; idx[p - 1] = ti;
                }
            }
        }
    }
    int ptr = 0;
    for (int r = 0; r < 8; r++) {
        u64 key = ~0ull;
        if (ptr < 8)
            key = ((u64)__float_as_uint(val[ptr]) << 32) | (unsigned)idx[ptr];
        u64 m = key;
        for (int off = 16; off; off >>= 1) {
            u64 o = __shfl_xor_sync(0xffffffffu, m, off);
            if (o < m) m = o;
        }
        if (lane == 0) neigh[gw * KNB + r] = (int)(m & 0xffffffffull);
        if (key == m) ptr++;
    }
}

// ---------------- sequential k-means: single warp, zero barriers -------------
__global__ void kmeans_kernel(const float* __restrict__ D, const int* __restrict__ perm,
                              int* __restrict__ assign_out) {
    __shared__ float S[KC * N_NODES];     // 32KB per-cluster running dist sums
    __shared__ float Drow_sh[N_NODES];    // 4KB current node's D row
    __shared__ int   sperm[N_NODES];      // 4KB
    __shared__ int   cent_sh[KC];
    const int lane = threadIdx.x;
    const int base = lane * 32;
    const float INF = __int_as_float(0x7f800000);
    const unsigned FULL = 0xffffffffu;

    for (int i = lane; i < N_NODES; i += 32) sperm[i] = perm[i];
    __syncwarp();
    if (lane < KC) cent_sh[lane] = sperm[lane];
    __syncwarp();
    // S[c] = D row of seed centroid c
    for (int c = 0; c < KC; c++) {
        const float* row = D + (size_t)cent_sh[c] * N_NODES;
#pragma unroll
        for (int j = 0; j < 8; j++)
            *(float4*)&S[c * N_NODES + base + j * 4] = *(const float4*)(row + base + j * 4);
    }
    // membership nibbles: nib value = cluster+1, 0 = unassigned
    unsigned nib[4] = {0u, 0u, 0u, 0u};
    for (int c = 0; c < KC; c++) {
        int p = sperm[c];
        if ((p >> 5) == lane) {
            int l = p & 31;
            nib[l >> 3] |= (unsigned)(c + 1) << ((l & 7) * 4);
        }
    }
    // preload row for step 0
    float4 cur[8];
    {
        const float* row = D + (size_t)sperm[KC] * N_NODES;
#pragma unroll
        for (int j = 0; j < 8; j++) cur[j] = *(const float4*)(row + base + j * 4);
#pragma unroll
        for (int j = 0; j < 8; j++) *(float4*)&Drow_sh[base + j * 4] = cur[j];
    }
    __syncwarp();

    for (int step = 0; step < NSTEPS; step++) {
        const int ni = sperm[KC + step];
        // prefetch next node's row (addresses known in advance)
        float4 nxt[8];
        {
            const int nn = sperm[KC + ((step + 1 < NSTEPS) ? step + 1 : step)];
            const float* row = D + (size_t)nn * N_NODES;
#pragma unroll
            for (int j = 0; j < 8; j++) nxt[j] = *(const float4*)(row + base + j * 4);
        }
        // pick nearest centroid (argmin over 8, first-index tiebreak)
        float cd = (lane < KC) ? Drow_sh[cent_sh[lane]] : INF;
        u64 key = ((u64)__float_as_uint(cd) << 32) | (unsigned)lane;
#pragma unroll
        for (int off = 4; off; off >>= 1) {
            u64 o = __shfl_xor_sync(FULL, key, off);
            if (o < key) key = o;
        }
        key = __shfl_sync(FULL, key, 0);
        const int c = (int)(key & 31u);
        const unsigned tgt = (unsigned)(c + 1);
        // S[c] += Drow; argmin of S over members (== argmin of S/denom)
        float* Sc = S + c * N_NODES + base;
        u64 best = ~0ull;
#pragma unroll
        for (int j = 0; j < 8; j++) {
            float4 s4 = *(float4*)(Sc + j * 4);
            float4 d4 = cur[j];
            s4.x += d4.x; s4.y += d4.y; s4.z += d4.z; s4.w += d4.w;
            *(float4*)(Sc + j * 4) = s4;
            unsigned nj = nib[j >> 1] >> ((j & 1) * 16);
            int i0 = base + j * 4;
            float sv[4] = {s4.x, s4.y, s4.z, s4.w};
#pragma unroll
            for (int t = 0; t < 4; t++) {
                bool memb = (((nj >> (t * 4)) & 15u) == tgt) | ((i0 + t) == ni);
                u64 k2 = memb ? (((u64)__float_as_uint(sv[t]) << 32) | (unsigned)(i0 + t))
                              : ~0ull;
                if (k2 < best) best = k2;
            }
        }
#pragma unroll
        for (int off = 16; off; off >>= 1) {
            u64 o = __shfl_xor_sync(FULL, best, off);
            if (o < best) best = o;
        }
        if (lane == 0) cent_sh[c] = (int)(best & 0xffffffffull);
        // record assignment of ni
        if ((ni >> 5) == lane) {
            int l = ni & 31;
            nib[l >> 3] |= tgt << ((l & 7) * 4);
        }
        // rotate prefetched row into place
#pragma unroll
        for (int j = 0; j < 8; j++) {
            *(float4*)&Drow_sh[base + j * 4] = nxt[j];
            cur[j] = nxt[j];
        }
        __syncwarp();
    }
#pragma unroll
    for (int w = 0; w < 4; w++)
#pragma unroll
        for (int t = 0; t < 8; t++) {
            int i = base + w * 8 + t;
            assign_out[i] = (int)((nib[w] >> (t * 4)) & 15u) - 1;
        }
}

// ---------------- E[e] = sum_{v in neigh(e)} xf[v] ---------------------------
__global__ void agg_local_kernel(const float* __restrict__ xf, const int* __restrict__ neigh,
                                 float* __restrict__ E) {
    int e = blockIdx.x;
    int nb[KNB];
#pragma unroll
    for (int j = 0; j < KNB; j++) nb[j] = neigh[e * KNB + j];
    for (int c = threadIdx.x; c < C_DIM; c += 256) {
        float s = 0.f;
#pragma unroll
        for (int j = 0; j < KNB; j++) s += xf[(size_t)nb[j] * C_DIM + c];
        E[(size_t)e * C_DIM + c] = s;
    }
}

// ---------------- E[n+c] = sum_{assign[v]==c} xf[v] --------------------------
__global__ void agg_global_kernel(const float* __restrict__ xf, const int* __restrict__ assign_,
                                  float* __restrict__ E) {
    __shared__ int sa[N_NODES];
    int tid = threadIdx.x;
    for (int i = tid; i < N_NODES; i += 256) sa[i] = assign_[i];
    __syncthreads();
    int c = blockIdx.x;
    int col = blockIdx.y * 256 + tid;
    float s = 0.f;
    for (int i = 0; i < N_NODES; i++)
        if (sa[i] == c) s += xf[(size_t)i * C_DIM + col];
    E[(size_t)(N_NODES + c) * C_DIM + col] = s;
}

// ---------------- Y[v] = sum_{e: v in neigh(e)} X1[e] + X1[n+assign[v]] ------
__global__ void agg_out_kernel(const float* __restrict__ X1, const int* __restrict__ neigh,
                               const int* __restrict__ assign_, float* __restrict__ Y) {
    int v = blockIdx.x;
    __shared__ int list[N_NODES];
    __shared__ int cnt_s;
    int tid = threadIdx.x, lane = tid & 31, wid = tid >> 5;
    if (wid == 0) {
        int cnt = 0;
        for (int base = 0; base < N_NODES; base += 32) {
            int e = base + lane;
            const int4* p = (const int4*)(neigh + e * KNB);
            int4 q0 = p[0], q1 = p[1];
            bool m = (q0.x == v) | (q0.y == v) | (q0.z == v) | (q0.w == v) |
                     (q1.x == v) | (q1.y == v) | (q1.z == v) | (q1.w == v);
            unsigned msk = __ballot_sync(0xffffffffu, m);
            if (m) list[cnt + __popc(msk & ((1u << lane) - 1u))] = e;
            cnt += __popc(msk);
        }
        if (lane == 0) cnt_s = cnt;
    }
    __syncthreads();
    int cnt = cnt_s;
    int ge = N_NODES + assign_[v];
    float s[8];
#pragma unroll
    for (int w = 0; w < 8; w++) s[w] = X1[(size_t)ge * C_DIM + tid + w * 256];
    for (int t = 0; t < cnt; t++) {
        const float* xr = X1 + (size_t)list[t] * C_DIM;
#pragma unroll
        for (int w = 0; w < 8; w++) s[w] += xr[tid + w * 256];
    }
#pragma unroll
    for (int w = 0; w < 8; w++) Y[(size_t)v * C_DIM + tid + w * 256] = s[w];
}

// ---------------- host launcher ----------------------------------------------
extern "C" void kernel_launch(void* const* d_in, const int* in_sizes, int n_in,
                              void* d_out, int out_size) {
    const float* x0  = (const float*)d_in[0];
    const float* wfc = (const float*)d_in[1];
    const float* bfc = (const float*)d_in[2];
    const float* w1  = (const float*)d_in[3];
    const float* w2  = (const float*)d_in[4];
    float* out = (float*)d_out;

    float *xf, *sq, *D, *E, *X1, *Y;
    int *neigh, *perm, *assign_;
    cudaGetSymbolAddress((void**)&xf,      g_xf);
    cudaGetSymbolAddress((void**)&sq,      g_sq);
    cudaGetSymbolAddress((void**)&D,       g_D);
    cudaGetSymbolAddress((void**)&neigh,   g_neigh);
    cudaGetSymbolAddress((void**)&perm,    g_perm);
    cudaGetSymbolAddress((void**)&assign_, g_assign);
    cudaGetSymbolAddress((void**)&E,       g_E);
    cudaGetSymbolAddress((void**)&X1,      g_X1);
    cudaGetSymbolAddress((void**)&Y,       g_Y);

    perm_kernel<<<1, 1024>>>(perm);
    sgemm_kernel<<<dim3(C_DIM / 128, N_NODES / 128), 256>>>(x0, wfc, bfc, xf,
                                                            N_NODES, C_DIM, C_DIM);
    rowsq_kernel<<<N_NODES, 256>>>(xf, sq);
    dist_kernel<<<dim3(N_NODES / 64, N_NODES / 128), 256>>>(xf, sq, D);
    knn_kernel<<<N_NODES / 8, 256>>>(D, neigh);
    kmeans_kernel<<<1, 32>>>(D, perm, assign_);
    agg_local_kernel<<<N_NODES, 256>>>(xf, neigh, E);
    agg_global_kernel<<<dim3(KC, C_DIM / 256), 256>>>(xf, assign_, E);
    sgemm_kernel<<<dim3(C_DIM / 128, (N_EDGES + 127) / 128), 256>>>(E, w1, nullptr, X1,
                                                                    N_EDGES, C_DIM, C_DIM);
    agg_out_kernel<<<N_NODES, 256>>>(X1, neigh, assign_, Y);
    sgemm_kernel<<<dim3(C_DIM / 128, N_NODES / 128), 256>>>(Y, w2, nullptr, out,
                                                            N_NODES, C_DIM, C_DIM);
}

// round 4
// speedup vs baseline: 1.3603x; 1.2166x over previous
#include <cuda_runtime.h>
#include <cstdint>
#include <cstddef>

#define N_NODES 1024
#define C_DIM   2048
#define KNB     8
#define KC      8
#define N_EDGES (N_NODES + KC)
#define NSTEPS  (N_NODES - KC)
#define E_PAD   1152   // padded edge-row count (9 * 128)

typedef unsigned long long u64;

// ---------------- scratch (static __device__, zero-initialized) --------------
__device__ float g_xf[N_NODES * C_DIM];
__device__ float g_sq[N_NODES];
__device__ float g_D[N_NODES * N_NODES];
__device__ int   g_neigh[N_NODES * KNB];
__device__ int   g_perm[N_NODES];
__device__ int   g_assign[N_NODES];
__device__ float g_E[E_PAD * C_DIM];    // rows 1032..1151 stay zero
__device__ float g_X1[E_PAD * C_DIM];
__device__ float g_Y[N_NODES * C_DIM];

// ---------------- helpers ----------------------------------------------------
__device__ __forceinline__ float to_tf32(float x) {
    uint32_t r;
    asm("cvt.rna.tf32.f32 %0, %1;" : "=r"(r) : "f"(x));
    return __uint_as_float(r);
}

#define MMA_TF32(d, a, b)                                                     \
    asm volatile(                                                             \
        "mma.sync.aligned.m16n8k8.row.col.f32.tf32.tf32.f32 "                 \
        "{%0,%1,%2,%3}, {%4,%5,%6,%7}, {%8,%9}, {%0,%1,%2,%3};"               \
        : "+f"((d)[0]), "+f"((d)[1]), "+f"((d)[2]), "+f"((d)[3])              \
        : "r"((a)[0]), "r"((a)[1]), "r"((a)[2]), "r"((a)[3]),                 \
          "r"((b)[0]), "r"((b)[1]))

// ---------------- threefry-2x32 (20 rounds) ----------------------------------
__device__ __forceinline__ void threefry2x32(unsigned k0, unsigned k1,
                                             unsigned& x0, unsigned& x1) {
    unsigned ks2 = k0 ^ k1 ^ 0x1BD11BDAu;
    x0 += k0; x1 += k1;
#define TF_R(r) { x0 += x1; x1 = (x1 << (r)) | (x1 >> (32 - (r))); x1 ^= x0; }
    TF_R(13) TF_R(15) TF_R(26) TF_R(6)
    x0 += k1;  x1 += ks2 + 1u;
    TF_R(17) TF_R(29) TF_R(16) TF_R(24)
    x0 += ks2; x1 += k0 + 2u;
    TF_R(13) TF_R(15) TF_R(26) TF_R(6)
    x0 += k0;  x1 += k1 + 3u;
    TF_R(17) TF_R(29) TF_R(16) TF_R(24)
    x0 += k1;  x1 += ks2 + 4u;
    TF_R(13) TF_R(15) TF_R(26) TF_R(6)
    x0 += ks2; x1 += k0 + 5u;
#undef TF_R
}

__global__ void perm_kernel(int* __restrict__ perm) {
    __shared__ u64 keys[N_NODES];
    int tid = threadIdx.x;
    unsigned s0, s1;
    { unsigned a0 = 0u, a1 = 1u; threefry2x32(0u, 42u, a0, a1); s0 = a0; s1 = a1; }
    if (tid < 512) {
        unsigned x0 = 0u, x1 = (unsigned)tid;
        threefry2x32(s0, s1, x0, x1);
        keys[tid] = ((u64)(x0 ^ x1) << 32) | (unsigned)tid;
        unsigned y0 = 0u, y1 = (unsigned)(tid + 512);
        threefry2x32(s0, s1, y0, y1);
        keys[tid + 512] = ((u64)(y0 ^ y1) << 32) | (unsigned)(tid + 512);
    }
    __syncthreads();
    for (int k = 2; k <= N_NODES; k <<= 1) {
        for (int j = k >> 1; j > 0; j >>= 1) {
            int ixj = tid ^ j;
            if (ixj > tid) {
                u64 a = keys[tid], b = keys[ixj];
                bool up = ((tid & k) == 0);
                if ((a > b) == up) { keys[tid] = b; keys[ixj] = a; }
            }
            __syncthreads();
        }
    }
    perm[tid] = (int)(keys[tid] & 0xffffffffull);
}

// ---------------- fp32 SGEMM (GEMM1 only): 128x128, 8x8/thread ---------------
__global__ __launch_bounds__(256) void sgemm_kernel(
    const float* __restrict__ A, const float* __restrict__ B,
    const float* __restrict__ bias, float* __restrict__ C,
    int M, int N, int K) {
    __shared__ float As[16][128];
    __shared__ float Bs[16][128];
    const int tid  = threadIdx.x;
    const int row0 = blockIdx.y * 128;
    const int col0 = blockIdx.x * 128;
    const int am = tid >> 2, ak = (tid & 3) << 2;
    const int bk = tid >> 5, bn = (tid & 31) << 2;
    const int ty = tid >> 4, tx = tid & 15;
    const float4 z4 = make_float4(0.f, 0.f, 0.f, 0.f);

    float4 a0, a1, b0, b1;
    {
        int r = row0 + am;
        a0 = (r      < M) ? *(const float4*)(A + (size_t)r        * K + ak) : z4;
        a1 = (r + 64 < M) ? *(const float4*)(A + (size_t)(r + 64) * K + ak) : z4;
        b0 = *(const float4*)(B + (size_t)bk       * N + col0 + bn);
        b1 = *(const float4*)(B + (size_t)(bk + 8) * N + col0 + bn);
    }
    float acc[8][8] = {};

#define STORE_TILES()                                                         \
    {                                                                         \
        As[ak + 0][am] = a0.x; As[ak + 1][am] = a0.y;                         \
        As[ak + 2][am] = a0.z; As[ak + 3][am] = a0.w;                         \
        As[ak + 0][am + 64] = a1.x; As[ak + 1][am + 64] = a1.y;               \
        As[ak + 2][am + 64] = a1.z; As[ak + 3][am + 64] = a1.w;               \
        *(float4*)&Bs[bk][bn]     = b0;                                       \
        *(float4*)&Bs[bk + 8][bn] = b1;                                       \
    }
#define COMPUTE_TILE()                                                        \
    _Pragma("unroll")                                                         \
    for (int kt = 0; kt < 16; kt++) {                                         \
        float af[8], bf[8];                                                   \
        *(float4*)&af[0] = *(const float4*)&As[kt][ty * 8];                   \
        *(float4*)&af[4] = *(const float4*)&As[kt][ty * 8 + 4];               \
        *(float4*)&bf[0] = *(const float4*)&Bs[kt][tx * 8];                   \
        *(float4*)&bf[4] = *(const float4*)&Bs[kt][tx * 8 + 4];               \
        _Pragma("unroll")                                                     \
        for (int i = 0; i < 8; i++)                                           \
            _Pragma("unroll")                                                 \
            for (int j = 0; j < 8; j++)                                       \
                acc[i][j] = fmaf(af[i], bf[j], acc[i][j]);                    \
    }

    STORE_TILES();
    __syncthreads();
    for (int k0 = 16; k0 < K; k0 += 16) {
        int r = row0 + am;
        a0 = (r      < M) ? *(const float4*)(A + (size_t)r        * K + k0 + ak) : z4;
        a1 = (r + 64 < M) ? *(const float4*)(A + (size_t)(r + 64) * K + k0 + ak) : z4;
        b0 = *(const float4*)(B + (size_t)(k0 + bk)     * N + col0 + bn);
        b1 = *(const float4*)(B + (size_t)(k0 + bk + 8) * N + col0 + bn);
        COMPUTE_TILE();
        __syncthreads();
        STORE_TILES();
        __syncthreads();
    }
    COMPUTE_TILE();

    float4 bias0 = z4, bias1 = z4;
    if (bias) {
        bias0 = *(const float4*)(bias + col0 + tx * 8);
        bias1 = *(const float4*)(bias + col0 + tx * 8 + 4);
    }
#pragma unroll
    for (int i = 0; i < 8; i++) {
        int r = row0 + ty * 8 + i;
        if (r < M) {
            float4 o0 = make_float4(acc[i][0] + bias0.x, acc[i][1] + bias0.y,
                                    acc[i][2] + bias0.z, acc[i][3] + bias0.w);
            float4 o1 = make_float4(acc[i][4] + bias1.x, acc[i][5] + bias1.y,
                                    acc[i][6] + bias1.z, acc[i][7] + bias1.w);
            *(float4*)(C + (size_t)r * N + col0 + tx * 8)     = o0;
            *(float4*)(C + (size_t)r * N + col0 + tx * 8 + 4) = o1;
        }
    }
#undef STORE_TILES
#undef COMPUTE_TILE
}

// ---------------- tf32 mma.sync GEMM: C[M,2048] = A[M,2048] @ B[2048,2048] ---
// 128x128 CTA tile, BK=32 double-buffered, 8 warps as 2(M)x4(N).
// A smem [128][36] (pad-36: conflict-free frag loads), B smem [32][128] XOR-swizzled.
#define AS_STRIDE 36
#define AS_STAGE  (128 * AS_STRIDE)
#define BS_STAGE  (32 * 128)

__global__ __launch_bounds__(256) void mma_gemm_kernel(
    const float* __restrict__ A, const float* __restrict__ B,
    float* __restrict__ C) {
    extern __shared__ float sm[];
    float* As = sm;                    // [2][128][36]
    float* Bs = sm + 2 * AS_STAGE;     // [2][32][128]
    const int tid  = threadIdx.x;
    const int lane = tid & 31, wid = tid >> 5;
    const int warp_m = wid >> 2, warp_n = wid & 3;
    const int g = lane >> 2, tig = lane & 3;
    const int row0 = blockIdx.y * 128, col0 = blockIdx.x * 128;

    float acc[4][4][4] = {};
    float4 ar[4], br[4];

#define LOADG(ks)                                                             \
    _Pragma("unroll")                                                         \
    for (int i = 0; i < 4; i++) {                                             \
        int ch = tid * 4 + i;                                                 \
        ar[i] = *(const float4*)(A + (size_t)(row0 + (ch >> 3)) * C_DIM       \
                                 + (ks) * 32 + (ch & 7) * 4);                 \
        br[i] = *(const float4*)(B + (size_t)((ks) * 32 + (ch >> 5)) * C_DIM  \
                                 + col0 + (ch & 31) * 4);                     \
    }

#define STORES(buf)                                                           \
    {                                                                         \
        float* Ab = As + (buf) * AS_STAGE;                                    \
        float* Bb = Bs + (buf) * BS_STAGE;                                    \
        _Pragma("unroll")                                                     \
        for (int i = 0; i < 4; i++) {                                         \
            int ch = tid * 4 + i;                                             \
            float4 v = ar[i];                                                 \
            v.x = to_tf32(v.x); v.y = to_tf32(v.y);                           \
            v.z = to_tf32(v.z); v.w = to_tf32(v.w);                           \
            *(float4*)(Ab + (ch >> 3) * AS_STRIDE + (ch & 7) * 4) = v;        \
            float4 w = br[i];                                                 \
            w.x = to_tf32(w.x); w.y = to_tf32(w.y);                           \
            w.z = to_tf32(w.z); w.w = to_tf32(w.w);                           \
            int kb = ch >> 5, n4 = ch & 31;                                   \
            *(float4*)(Bb + kb * 128 + ((n4 * 4) ^ ((kb & 3) << 3))) = w;     \
        }                                                                     \
    }

#define COMPUTE(buf)                                                          \
    {                                                                         \
        const float* Ab = As + (buf) * AS_STAGE;                              \
        const float* Bb = Bs + (buf) * BS_STAGE;                              \
        _Pragma("unroll")                                                     \
        for (int kk = 0; kk < 4; kk++) {                                      \
            uint32_t af[4][4], bf[4][2];                                      \
            const int k1 = kk * 8 + tig, k2 = kk * 8 + tig + 4;               \
            _Pragma("unroll")                                                 \
            for (int mt = 0; mt < 4; mt++) {                                  \
                int m0 = warp_m * 64 + mt * 16;                               \
                af[mt][0] = __float_as_uint(Ab[(m0 + g)     * AS_STRIDE + k1]); \
                af[mt][1] = __float_as_uint(Ab[(m0 + 8 + g) * AS_STRIDE + k1]); \
                af[mt][2] = __float_as_uint(Ab[(m0 + g)     * AS_STRIDE + k2]); \
                af[mt][3] = __float_as_uint(Ab[(m0 + 8 + g) * AS_STRIDE + k2]); \
            }                                                                 \
            _Pragma("unroll")                                                 \
            for (int nt = 0; nt < 4; nt++) {                                  \
                int n0 = warp_n * 32 + nt * 8;                                \
                bf[nt][0] = __float_as_uint(Bb[k1 * 128 + ((n0 + g) ^ (tig << 3))]); \
                bf[nt][1] = __float_as_uint(Bb[k2 * 128 + ((n0 + g) ^ (tig << 3))]); \
            }                                                                 \
            _Pragma("unroll")                                                 \
            for (int mt = 0; mt < 4; mt++)                                    \
                _Pragma("unroll")                                             \
                for (int nt = 0; nt < 4; nt++)                                \
                    MMA_TF32(acc[mt][nt], af[mt], bf[nt]);                    \
        }                                                                     \
    }

    LOADG(0);
    STORES(0);
    __syncthreads();
    for (int ks = 0; ks < 64; ks++) {
        const int cur = ks & 1;
        if (ks < 63) { LOADG(ks + 1); }
        COMPUTE(cur);
        if (ks < 63) { STORES(cur ^ 1); }
        __syncthreads();
    }

#pragma unroll
    for (int mt = 0; mt < 4; mt++) {
#pragma unroll
        for (int nt = 0; nt < 4; nt++) {
            int r  = row0 + warp_m * 64 + mt * 16 + g;
            int cc = col0 + warp_n * 32 + nt * 8 + tig * 2;
            *(float2*)(C + (size_t)r * C_DIM + cc) =
                make_float2(acc[mt][nt][0], acc[mt][nt][1]);
            *(float2*)(C + (size_t)(r + 8) * C_DIM + cc) =
                make_float2(acc[mt][nt][2], acc[mt][nt][3]);
        }
    }
#undef LOADG
#undef STORES
#undef COMPUTE
}

// ---------------- row squared norms ------------------------------------------
__global__ void rowsq_kernel(const float* __restrict__ xf, float* __restrict__ sq) {
    int row = blockIdx.x, tid = threadIdx.x;
    const float* x = xf + (size_t)row * C_DIM;
    float s = 0.f;
    for (int c = tid; c < C_DIM; c += 256) { float v = x[c]; s = fmaf(v, v, s); }
    for (int off = 16; off; off >>= 1) s += __shfl_xor_sync(0xffffffffu, s, off);
    __shared__ float r[8];
    if ((tid & 31) == 0) r[tid >> 5] = s;
    __syncthreads();
    if (tid == 0) { float t = 0.f; for (int w = 0; w < 8; w++) t += r[w]; sq[row] = t; }
}

// ---------------- pairwise distance: 128x64 tile, 8x4/thread -----------------
__global__ __launch_bounds__(256) void dist_kernel(
    const float* __restrict__ xf, const float* __restrict__ sq,
    float* __restrict__ D) {
    __shared__ float As[16][128];
    __shared__ float Bs[16][64];
    const int tid  = threadIdx.x;
    const int row0 = blockIdx.y * 128;
    const int col0 = blockIdx.x * 64;
    const int am = tid >> 2, ak = (tid & 3) << 2;
    const int ty = tid >> 4, tx = tid & 15;

    float4 a0, a1, b0;
    {
        a0 = *(const float4*)(xf + (size_t)(row0 + am)      * C_DIM + ak);
        a1 = *(const float4*)(xf + (size_t)(row0 + am + 64) * C_DIM + ak);
        b0 = *(const float4*)(xf + (size_t)(col0 + am)      * C_DIM + ak);
    }
    float acc[8][4] = {};

#define D_STORE()                                                             \
    {                                                                         \
        As[ak + 0][am] = a0.x; As[ak + 1][am] = a0.y;                         \
        As[ak + 2][am] = a0.z; As[ak + 3][am] = a0.w;                         \
        As[ak + 0][am + 64] = a1.x; As[ak + 1][am + 64] = a1.y;               \
        As[ak + 2][am + 64] = a1.z; As[ak + 3][am + 64] = a1.w;               \
        if (am < 64) {                                                        \
            Bs[ak + 0][am] = b0.x; Bs[ak + 1][am] = b0.y;                     \
            Bs[ak + 2][am] = b0.z; Bs[ak + 3][am] = b0.w;                     \
        }                                                                     \
    }
#define D_COMPUTE()                                                           \
    _Pragma("unroll")                                                         \
    for (int kt = 0; kt < 16; kt++) {                                         \
        float af[8], bf[4];                                                   \
        *(float4*)&af[0] = *(const float4*)&As[kt][ty * 8];                   \
        *(float4*)&af[4] = *(const float4*)&As[kt][ty * 8 + 4];               \
        *(float4*)&bf[0] = *(const float4*)&Bs[kt][tx * 4];                   \
        _Pragma("unroll")                                                     \
        for (int i = 0; i < 8; i++)                                           \
            _Pragma("unroll")                                                 \
            for (int j = 0; j < 4; j++)                                       \
                acc[i][j] = fmaf(af[i], bf[j], acc[i][j]);                    \
    }

    D_STORE();
    __syncthreads();
    for (int k0 = 16; k0 < C_DIM; k0 += 16) {
        a0 = *(const float4*)(xf + (size_t)(row0 + am)      * C_DIM + k0 + ak);
        a1 = *(const float4*)(xf + (size_t)(row0 + am + 64) * C_DIM + k0 + ak);
        b0 = *(const float4*)(xf + (size_t)(col0 + am)      * C_DIM + k0 + ak);
        D_COMPUTE();
        __syncthreads();
        D_STORE();
        __syncthreads();
    }
    D_COMPUTE();

#pragma unroll
    for (int i = 0; i < 8; i++) {
        int r = row0 + ty * 8 + i;
        float sqr = sq[r];
        float4 o;
        int c = col0 + tx * 4;
        o.x = sqrtf(fmaxf(sqr + sq[c + 0] - 2.f * acc[i][0], 0.f));
        o.y = sqrtf(fmaxf(sqr + sq[c + 1] - 2.f * acc[i][1], 0.f));
        o.z = sqrtf(fmaxf(sqr + sq[c + 2] - 2.f * acc[i][2], 0.f));
        o.w = sqrtf(fmaxf(sqr + sq[c + 3] - 2.f * acc[i][3], 0.f));
        *(float4*)(D + (size_t)r * N_NODES + c) = o;
    }
#undef D_STORE
#undef D_COMPUTE
}

// ---------------- kNN: 8 smallest per row (diag excluded), redux merge -------
__global__ void knn_kernel(const float* __restrict__ D, int* __restrict__ neigh) {
    int gw = (blockIdx.x * blockDim.x + threadIdx.x) >> 5;
    int lane = threadIdx.x & 31;
    if (gw >= N_NODES) return;
    const float* row = D + (size_t)gw * N_NODES;
    float val[8]; int idx[8];
#pragma unroll
    for (int r = 0; r < 8; r++) { val[r] = __int_as_float(0x7f800000); idx[r] = 0; }
    for (int j = lane; j < N_NODES; j += 32) {
        if (j == gw) continue;
        float v = row[j];
        if (v < val[7]) {
            val[7] = v; idx[7] = j;
#pragma unroll
            for (int p = 7; p > 0; p--) {
                if (val[p] < val[p - 1]) {
                    float tv = val[p]; val[p] = val[p - 1]; val[p - 1] = tv;
                    int   ti = idx[p]; idx[p] = idx[p - 1]; idx[p - 1] = ti;
                }
            }
        }
    }
    int ptr = 0;
#pragma unroll
    for (int r = 0; r < 8; r++) {
        unsigned vb = (ptr < 8) ? __float_as_uint(val[ptr]) : 0x7f800000u;
        unsigned vm = __reduce_min_sync(0xffffffffu, vb);
        unsigned mi = (ptr < 8 && vb == vm) ? (unsigned)idx[ptr] : 0x7fffffffu;
        unsigned im = __reduce_min_sync(0xffffffffu, mi);
        if (lane == 0) neigh[gw * KNB + r] = (int)im;
        if (ptr < 8 && vb == vm && (unsigned)idx[ptr] == im) ptr++;
    }
}

// ---------------- sequential k-means: single warp, tree argmin ---------------
__global__ void kmeans_kernel(const float* __restrict__ D, const int* __restrict__ perm,
                              int* __restrict__ assign_out) {
    __shared__ float S[KC * N_NODES];
    __shared__ float Drow_sh[N_NODES];
    __shared__ int   sperm[N_NODES];
    const int lane = threadIdx.x;
    const int base = lane * 32;
    const float INF = __int_as_float(0x7f800000);
    const unsigned FULL = 0xffffffffu;

    for (int i = lane; i < N_NODES; i += 32) sperm[i] = perm[i];
    __syncwarp();
    int mycent = (lane < KC) ? sperm[lane] : 0;
    for (int c = 0; c < KC; c++) {
        const float* row = D + (size_t)sperm[c] * N_NODES;
#pragma unroll
        for (int j = 0; j < 8; j++)
            *(float4*)&S[c * N_NODES + base + j * 4] = *(const float4*)(row + base + j * 4);
    }
    unsigned nib[4] = {0u, 0u, 0u, 0u};
    for (int c = 0; c < KC; c++) {
        int p = sperm[c];
        if ((p >> 5) == lane) nib[(p & 31) >> 3] |= (unsigned)(c + 1) << (((p & 31) & 7) * 4);
    }
    float4 cur[8];
    {
        const float* row = D + (size_t)sperm[KC] * N_NODES;
#pragma unroll
        for (int j = 0; j < 8; j++) {
            cur[j] = *(const float4*)(row + base + j * 4);
            *(float4*)&Drow_sh[base + j * 4] = cur[j];
        }
    }
    __syncwarp();

    for (int step = 0; step < NSTEPS; step++) {
        const int ni = sperm[KC + step];
        // prefetch next node's row (address known in advance)
        float4 nxt[8];
        {
            const int nn = sperm[KC + ((step + 1 < NSTEPS) ? step + 1 : step)];
            const float* row = D + (size_t)nn * N_NODES;
#pragma unroll
            for (int j = 0; j < 8; j++) nxt[j] = *(const float4*)(row + base + j * 4);
        }
        // nearest centroid: redux argmin over 8 lanes (first-index tiebreak)
        unsigned cb = (lane < KC) ? __float_as_uint(Drow_sh[mycent]) : 0x7f800000u;
        unsigned cm = __reduce_min_sync(FULL, cb);
        unsigned cmask = __ballot_sync(FULL, cb == cm);
        const int c = __ffs(cmask) - 1;
        const unsigned tgt = (unsigned)(c + 1);
        // S[c] += Drow; masked values (argmin of S over members == argmin of mean)
        float* Sc = S + c * N_NODES + base;
        float vv[32];
#pragma unroll
        for (int j = 0; j < 8; j++) {
            float4 s4 = *(float4*)(Sc + j * 4);
            float4 d4 = cur[j];
            s4.x += d4.x; s4.y += d4.y; s4.z += d4.z; s4.w += d4.w;
            *(float4*)(Sc + j * 4) = s4;
            unsigned nj = nib[j >> 1] >> ((j & 1) * 16);
            int i0 = base + j * 4;
            vv[j * 4 + 0] = ((((nj >>  0) & 15u) == tgt) | (i0 + 0 == ni)) ? s4.x : INF;
            vv[j * 4 + 1] = ((((nj >>  4) & 15u) == tgt) | (i0 + 1 == ni)) ? s4.y : INF;
            vv[j * 4 + 2] = ((((nj >>  8) & 15u) == tgt) | (i0 + 2 == ni)) ? s4.z : INF;
            vv[j * 4 + 3] = ((((nj >> 12) & 15u) == tgt) | (i0 + 3 == ni)) ? s4.w : INF;
        }
        // tree min over 32 (depth 5), then equality mask for first index
        float tm[16];
#pragma unroll
        for (int t = 0; t < 16; t++) tm[t] = fminf(vv[t], vv[t + 16]);
#pragma unroll
        for (int t = 0; t < 8; t++)  tm[t] = fminf(tm[t], tm[t + 8]);
#pragma unroll
        for (int t = 0; t < 4; t++)  tm[t] = fminf(tm[t], tm[t + 4]);
        tm[0] = fminf(tm[0], tm[2]); tm[1] = fminf(tm[1], tm[3]);
        const float minv = fminf(tm[0], tm[1]);
        unsigned msk = 0u;
#pragma unroll
        for (int j = 0; j < 32; j++) msk |= (vv[j] == minv) ? (1u << j) : 0u;
        const int besti = base + __ffs(msk) - 1;
        unsigned bb = __float_as_uint(minv);
        unsigned bm = __reduce_min_sync(FULL, bb);
        unsigned wmask = __ballot_sync(FULL, bb == bm);
        int src = __ffs(wmask) - 1;
        int newc = __shfl_sync(FULL, besti, src);
        if (lane == c) mycent = newc;
        if ((ni >> 5) == lane) nib[(ni & 31) >> 3] |= tgt << (((ni & 31) & 7) * 4);
#pragma unroll
        for (int j = 0; j < 8; j++) {
            *(float4*)&Drow_sh[base + j * 4] = nxt[j];
            cur[j] = nxt[j];
        }
        __syncwarp();
    }
#pragma unroll
    for (int w = 0; w < 4; w++)
#pragma unroll
        for (int t = 0; t < 8; t++)
            assign_out[base + w * 8 + t] = (int)((nib[w] >> (t * 4)) & 15u) - 1;
}

// ---------------- E[e] = sum_{v in neigh(e)} xf[v] ---------------------------
__global__ void agg_local_kernel(const float* __restrict__ xf, const int* __restrict__ neigh,
                                 float* __restrict__ E) {
    int e = blockIdx.x;
    int nb[KNB];
#pragma unroll
    for (int j = 0; j < KNB; j++) nb[j] = neigh[e * KNB + j];
    for (int c = threadIdx.x; c < C_DIM; c += 256) {
        float s = 0.f;
#pragma unroll
        for (int j = 0; j < KNB; j++) s += xf[(size_t)nb[j] * C_DIM + c];
        E[(size_t)e * C_DIM + c] = s;
    }
}

// ---------------- E[n+c] = sum_{assign[v]==c} xf[v] --------------------------
__global__ void agg_global_kernel(const float* __restrict__ xf, const int* __restrict__ assign_,
                                  float* __restrict__ E) {
    __shared__ int sa[N_NODES];
    int tid = threadIdx.x;
    for (int i = tid; i < N_NODES; i += 256) sa[i] = assign_[i];
    __syncthreads();
    int c = blockIdx.x;
    int col = blockIdx.y * 256 + tid;
    float s = 0.f;
    for (int i = 0; i < N_NODES; i++)
        if (sa[i] == c) s += xf[(size_t)i * C_DIM + col];
    E[(size_t)(N_NODES + c) * C_DIM + col] = s;
}

// ---------------- Y[v] = sum_{e: v in neigh(e)} X1[e] + X1[n+assign[v]] ------
__global__ void agg_out_kernel(const float* __restrict__ X1, const int* __restrict__ neigh,
                               const int* __restrict__ assign_, float* __restrict__ Y) {
    int v = blockIdx.x;
    __shared__ int list[N_NODES];
    __shared__ int cnt_s;
    int tid = threadIdx.x, lane = tid & 31, wid = tid >> 5;
    if (wid == 0) {
        int cnt = 0;
        for (int base = 0; base < N_NODES; base += 32) {
            int e = base + lane;
            const int4* p = (const int4*)(neigh + e * KNB);
            int4 q0 = p[0], q1 = p[1];
            bool m = (q0.x == v) | (q0.y == v) | (q0.z == v) | (q0.w == v) |
                     (q1.x == v) | (q1.y == v) | (q1.z == v) | (q1.w == v);
            unsigned msk = __ballot_sync(0xffffffffu, m);
            if (m) list[cnt + __popc(msk & ((1u << lane) - 1u))] = e;
            cnt += __popc(msk);
        }
        if (lane == 0) cnt_s = cnt;
    }
    __syncthreads();
    int cnt = cnt_s;
    int ge = N_NODES + assign_[v];
    float s[8];
#pragma unroll
    for (int w = 0; w < 8; w++) s[w] = X1[(size_t)ge * C_DIM + tid + w * 256];
    for (int t = 0; t < cnt; t++) {
        const float* xr = X1 + (size_t)list[t] * C_DIM;
#pragma unroll
        for (int w = 0; w < 8; w++) s[w] += xr[tid + w * 256];
    }
#pragma unroll
    for (int w = 0; w < 8; w++) Y[(size_t)v * C_DIM + tid + w * 256] = s[w];
}

// ---------------- host launcher ----------------------------------------------
extern "C" void kernel_launch(void* const* d_in, const int* in_sizes, int n_in,
                              void* d_out, int out_size) {
    const float* x0  = (const float*)d_in[0];
    const float* wfc = (const float*)d_in[1];
    const float* bfc = (const float*)d_in[2];
    const float* w1  = (const float*)d_in[3];
    const float* w2  = (const float*)d_in[4];
    float* out = (float*)d_out;

    float *xf, *sq, *D, *E, *X1, *Y;
    int *neigh, *perm, *assign_;
    cudaGetSymbolAddress((void**)&xf,      g_xf);
    cudaGetSymbolAddress((void**)&sq,      g_sq);
    cudaGetSymbolAddress((void**)&D,       g_D);
    cudaGetSymbolAddress((void**)&neigh,   g_neigh);
    cudaGetSymbolAddress((void**)&perm,    g_perm);
    cudaGetSymbolAddress((void**)&assign_, g_assign);
    cudaGetSymbolAddress((void**)&E,       g_E);
    cudaGetSymbolAddress((void**)&X1,      g_X1);
    cudaGetSymbolAddress((void**)&Y,       g_Y);

    const size_t dynsmem = (2 * AS_STAGE + 2 * BS_STAGE) * sizeof(float);  // 69632
    cudaFuncSetAttribute(mma_gemm_kernel,
                         cudaFuncAttributeMaxDynamicSharedMemorySize, (int)dynsmem);

    perm_kernel<<<1, 1024>>>(perm);
    sgemm_kernel<<<dim3(C_DIM / 128, N_NODES / 128), 256>>>(x0, wfc, bfc, xf,
                                                            N_NODES, C_DIM, C_DIM);
    rowsq_kernel<<<N_NODES, 256>>>(xf, sq);
    dist_kernel<<<dim3(N_NODES / 64, N_NODES / 128), 256>>>(xf, sq, D);
    knn_kernel<<<N_NODES / 8, 256>>>(D, neigh);
    kmeans_kernel<<<1, 32>>>(D, perm, assign_);
    agg_local_kernel<<<N_NODES, 256>>>(xf, neigh, E);
    agg_global_kernel<<<dim3(KC, C_DIM / 256), 256>>>(xf, assign_, E);
    mma_gemm_kernel<<<dim3(C_DIM / 128, E_PAD / 128), 256, dynsmem>>>(E, w1, X1);
    agg_out_kernel<<<N_NODES, 256>>>(X1, neigh, assign_, Y);
    mma_gemm_kernel<<<dim3(C_DIM / 128, N_NODES / 128), 256, dynsmem>>>(Y, w2, out);
}

// round 5
// speedup vs baseline: 1.5976x; 1.1745x over previous
#include <cuda_runtime.h>
#include <cstdint>
#include <cstddef>

#define N_NODES 1024
#define C_DIM   2048
#define KNB     8
#define KC      8
#define N_EDGES (N_NODES + KC)
#define NSTEPS  (N_NODES - KC)
#define E_PAD   1152   // padded edge-row count (9 * 128)

typedef unsigned long long u64;

// ---------------- scratch (static __device__, zero-initialized) --------------
__device__ float g_xf[N_NODES * C_DIM];
__device__ float g_sq[N_NODES];
__device__ float g_D[N_NODES * N_NODES];
__device__ int   g_neigh[N_NODES * KNB];
__device__ int   g_perm[N_NODES];
__device__ int   g_assign[N_NODES];
__device__ float g_E[E_PAD * C_DIM];    // rows 1032..1151 stay zero
__device__ float g_X1[E_PAD * C_DIM];
__device__ float g_Y[N_NODES * C_DIM];

// ---------------- helpers ----------------------------------------------------
__device__ __forceinline__ float to_tf32(float x) {
    uint32_t r;
    asm("cvt.rna.tf32.f32 %0, %1;" : "=r"(r) : "f"(x));
    return __uint_as_float(r);
}

#define MMA_TF32(d, a, b)                                                     \
    asm volatile(                                                             \
        "mma.sync.aligned.m16n8k8.row.col.f32.tf32.tf32.f32 "                 \
        "{%0,%1,%2,%3}, {%4,%5,%6,%7}, {%8,%9}, {%0,%1,%2,%3};"               \
        : "+f"((d)[0]), "+f"((d)[1]), "+f"((d)[2]), "+f"((d)[3])              \
        : "r"((a)[0]), "r"((a)[1]), "r"((a)[2]), "r"((a)[3]),                 \
          "r"((b)[0]), "r"((b)[1]))

// ---------------- threefry-2x32 (20 rounds) ----------------------------------
__device__ __forceinline__ void threefry2x32(unsigned k0, unsigned k1,
                                             unsigned& x0, unsigned& x1) {
    unsigned ks2 = k0 ^ k1 ^ 0x1BD11BDAu;
    x0 += k0; x1 += k1;
#define TF_R(r) { x0 += x1; x1 = (x1 << (r)) | (x1 >> (32 - (r))); x1 ^= x0; }
    TF_R(13) TF_R(15) TF_R(26) TF_R(6)
    x0 += k1;  x1 += ks2 + 1u;
    TF_R(17) TF_R(29) TF_R(16) TF_R(24)
    x0 += ks2; x1 += k0 + 2u;
    TF_R(13) TF_R(15) TF_R(26) TF_R(6)
    x0 += k0;  x1 += k1 + 3u;
    TF_R(17) TF_R(29) TF_R(16) TF_R(24)
    x0 += k1;  x1 += ks2 + 4u;
    TF_R(13) TF_R(15) TF_R(26) TF_R(6)
    x0 += ks2; x1 += k0 + 5u;
#undef TF_R
}

__global__ void perm_kernel(int* __restrict__ perm) {
    __shared__ u64 keys[N_NODES];
    int tid = threadIdx.x;
    unsigned s0, s1;
    { unsigned a0 = 0u, a1 = 1u; threefry2x32(0u, 42u, a0, a1); s0 = a0; s1 = a1; }
    if (tid < 512) {
        unsigned x0 = 0u, x1 = (unsigned)tid;
        threefry2x32(s0, s1, x0, x1);
        keys[tid] = ((u64)(x0 ^ x1) << 32) | (unsigned)tid;
        unsigned y0 = 0u, y1 = (unsigned)(tid + 512);
        threefry2x32(s0, s1, y0, y1);
        keys[tid + 512] = ((u64)(y0 ^ y1) << 32) | (unsigned)(tid + 512);
    }
    __syncthreads();
    for (int k = 2; k <= N_NODES; k <<= 1) {
        for (int j = k >> 1; j > 0; j >>= 1) {
            int ixj = tid ^ j;
            if (ixj > tid) {
                u64 a = keys[tid], b = keys[ixj];
                bool up = ((tid & k) == 0);
                if ((a > b) == up) { keys[tid] = b; keys[ixj] = a; }
            }
            __syncthreads();
        }
    }
    perm[tid] = (int)(keys[tid] & 0xffffffffull);
}

// ---------------- fp32 SGEMM (GEMM1 only): 128x128, 8x8/thread ---------------
__global__ __launch_bounds__(256) void sgemm_kernel(
    const float* __restrict__ A, const float* __restrict__ B,
    const float* __restrict__ bias, float* __restrict__ C,
    int M, int N, int K) {
    __shared__ float As[16][128];
    __shared__ float Bs[16][128];
    const int tid  = threadIdx.x;
    const int row0 = blockIdx.y * 128;
    const int col0 = blockIdx.x * 128;
    const int am = tid >> 2, ak = (tid & 3) << 2;
    const int bk = tid >> 5, bn = (tid & 31) << 2;
    const int ty = tid >> 4, tx = tid & 15;
    const float4 z4 = make_float4(0.f, 0.f, 0.f, 0.f);

    float4 a0, a1, b0, b1;
    {
        int r = row0 + am;
        a0 = (r      < M) ? *(const float4*)(A + (size_t)r        * K + ak) : z4;
        a1 = (r + 64 < M) ? *(const float4*)(A + (size_t)(r + 64) * K + ak) : z4;
        b0 = *(const float4*)(B + (size_t)bk       * N + col0 + bn);
        b1 = *(const float4*)(B + (size_t)(bk + 8) * N + col0 + bn);
    }
    float acc[8][8] = {};

#define STORE_TILES()                                                         \
    {                                                                         \
        As[ak + 0][am] = a0.x; As[ak + 1][am] = a0.y;                         \
        As[ak + 2][am] = a0.z; As[ak + 3][am] = a0.w;                         \
        As[ak + 0][am + 64] = a1.x; As[ak + 1][am + 64] = a1.y;               \
        As[ak + 2][am + 64] = a1.z; As[ak + 3][am + 64] = a1.w;               \
        *(float4*)&Bs[bk][bn]     = b0;                                       \
        *(float4*)&Bs[bk + 8][bn] = b1;                                       \
    }
#define COMPUTE_TILE()                                                        \
    _Pragma("unroll")                                                         \
    for (int kt = 0; kt < 16; kt++) {                                         \
        float af[8], bf[8];                                                   \
        *(float4*)&af[0] = *(const float4*)&As[kt][ty * 8];                   \
        *(float4*)&af[4] = *(const float4*)&As[kt][ty * 8 + 4];               \
        *(float4*)&bf[0] = *(const float4*)&Bs[kt][tx * 8];                   \
        *(float4*)&bf[4] = *(const float4*)&Bs[kt][tx * 8 + 4];               \
        _Pragma("unroll")                                                     \
        for (int i = 0; i < 8; i++)                                           \
            _Pragma("unroll")                                                 \
            for (int j = 0; j < 8; j++)                                       \
                acc[i][j] = fmaf(af[i], bf[j], acc[i][j]);                    \
    }

    STORE_TILES();
    __syncthreads();
    for (int k0 = 16; k0 < K; k0 += 16) {
        int r = row0 + am;
        a0 = (r      < M) ? *(const float4*)(A + (size_t)r        * K + k0 + ak) : z4;
        a1 = (r + 64 < M) ? *(const float4*)(A + (size_t)(r + 64) * K + k0 + ak) : z4;
        b0 = *(const float4*)(B + (size_t)(k0 + bk)     * N + col0 + bn);
        b1 = *(const float4*)(B + (size_t)(k0 + bk + 8) * N + col0 + bn);
        COMPUTE_TILE();
        __syncthreads();
        STORE_TILES();
        __syncthreads();
    }
    COMPUTE_TILE();

    float4 bias0 = z4, bias1 = z4;
    if (bias) {
        bias0 = *(const float4*)(bias + col0 + tx * 8);
        bias1 = *(const float4*)(bias + col0 + tx * 8 + 4);
    }
#pragma unroll
    for (int i = 0; i < 8; i++) {
        int r = row0 + ty * 8 + i;
        if (r < M) {
            float4 o0 = make_float4(acc[i][0] + bias0.x, acc[i][1] + bias0.y,
                                    acc[i][2] + bias0.z, acc[i][3] + bias0.w);
            float4 o1 = make_float4(acc[i][4] + bias1.x, acc[i][5] + bias1.y,
                                    acc[i][6] + bias1.z, acc[i][7] + bias1.w);
            *(float4*)(C + (size_t)r * N + col0 + tx * 8)     = o0;
            *(float4*)(C + (size_t)r * N + col0 + tx * 8 + 4) = o1;
        }
    }
#undef STORE_TILES
#undef COMPUTE_TILE
}

// ---------------- tf32 mma.sync GEMM: C[M,2048] = A[M,2048] @ B[2048,2048] ---
#define AS_STRIDE 36
#define AS_STAGE  (128 * AS_STRIDE)
#define BS_STAGE  (32 * 128)

__global__ __launch_bounds__(256) void mma_gemm_kernel(
    const float* __restrict__ A, const float* __restrict__ B,
    float* __restrict__ C) {
    extern __shared__ float sm[];
    float* As = sm;                    // [2][128][36]
    float* Bs = sm + 2 * AS_STAGE;     // [2][32][128]
    const int tid  = threadIdx.x;
    const int lane = tid & 31, wid = tid >> 5;
    const int warp_m = wid >> 2, warp_n = wid & 3;
    const int g = lane >> 2, tig = lane & 3;
    const int row0 = blockIdx.y * 128, col0 = blockIdx.x * 128;

    float acc[4][4][4] = {};
    float4 ar[4], br[4];

#define LOADG(ks)                                                             \
    _Pragma("unroll")                                                         \
    for (int i = 0; i < 4; i++) {                                             \
        int ch = tid * 4 + i;                                                 \
        ar[i] = *(const float4*)(A + (size_t)(row0 + (ch >> 3)) * C_DIM       \
                                 + (ks) * 32 + (ch & 7) * 4);                 \
        br[i] = *(const float4*)(B + (size_t)((ks) * 32 + (ch >> 5)) * C_DIM  \
                                 + col0 + (ch & 31) * 4);                     \
    }

#define STORES(buf)                                                           \
    {                                                                         \
        float* Ab = As + (buf) * AS_STAGE;                                    \
        float* Bb = Bs + (buf) * BS_STAGE;                                    \
        _Pragma("unroll")                                                     \
        for (int i = 0; i < 4; i++) {                                         \
            int ch = tid * 4 + i;                                             \
            float4 v = ar[i];                                                 \
            v.x = to_tf32(v.x); v.y = to_tf32(v.y);                           \
            v.z = to_tf32(v.z); v.w = to_tf32(v.w);                           \
            *(float4*)(Ab + (ch >> 3) * AS_STRIDE + (ch & 7) * 4) = v;        \
            float4 w = br[i];                                                 \
            w.x = to_tf32(w.x); w.y = to_tf32(w.y);                           \
            w.z = to_tf32(w.z); w.w = to_tf32(w.w);                           \
            int kb = ch >> 5, n4 = ch & 31;                                   \
            *(float4*)(Bb + kb * 128 + ((n4 * 4) ^ ((kb & 3) << 3))) = w;     \
        }                                                                     \
    }

#define COMPUTE(buf)                                                          \
    {                                                                         \
        const float* Ab = As + (buf) * AS_STAGE;                              \
        const float* Bb = Bs + (buf) * BS_STAGE;                              \
        _Pragma("unroll")                                                     \
        for (int kk = 0; kk < 4; kk++) {                                      \
            uint32_t af[4][4], bf[4][2];                                      \
            const int k1 = kk * 8 + tig, k2 = kk * 8 + tig + 4;               \
            _Pragma("unroll")                                                 \
            for (int mt = 0; mt < 4; mt++) {                                  \
                int m0 = warp_m * 64 + mt * 16;                               \
                af[mt][0] = __float_as_uint(Ab[(m0 + g)     * AS_STRIDE + k1]); \
                af[mt][1] = __float_as_uint(Ab[(m0 + 8 + g) * AS_STRIDE + k1]); \
                af[mt][2] = __float_as_uint(Ab[(m0 + g)     * AS_STRIDE + k2]); \
                af[mt][3] = __float_as_uint(Ab[(m0 + 8 + g) * AS_STRIDE + k2]); \
            }                                                                 \
            _Pragma("unroll")                                                 \
            for (int nt = 0; nt < 4; nt++) {                                  \
                int n0 = warp_n * 32 + nt * 8;                                \
                bf[nt][0] = __float_as_uint(Bb[k1 * 128 + ((n0 + g) ^ (tig << 3))]); \
                bf[nt][1] = __float_as_uint(Bb[k2 * 128 + ((n0 + g) ^ (tig << 3))]); \
            }                                                                 \
            _Pragma("unroll")                                                 \
            for (int mt = 0; mt < 4; mt++)                                    \
                _Pragma("unroll")                                             \
                for (int nt = 0; nt < 4; nt++)                                \
                    MMA_TF32(acc[mt][nt], af[mt], bf[nt]);                    \
        }                                                                     \
    }

    LOADG(0);
    STORES(0);
    __syncthreads();
    for (int ks = 0; ks < 64; ks++) {
        const int cur = ks & 1;
        if (ks < 63) { LOADG(ks + 1); }
        COMPUTE(cur);
        if (ks < 63) { STORES(cur ^ 1); }
        __syncthreads();
    }

#pragma unroll
    for (int mt = 0; mt < 4; mt++) {
#pragma unroll
        for (int nt = 0; nt < 4; nt++) {
            int r  = row0 + warp_m * 64 + mt * 16 + g;
            int cc = col0 + warp_n * 32 + nt * 8 + tig * 2;
            *(float2*)(C + (size_t)r * C_DIM + cc) =
                make_float2(acc[mt][nt][0], acc[mt][nt][1]);
            *(float2*)(C + (size_t)(r + 8) * C_DIM + cc) =
                make_float2(acc[mt][nt][2], acc[mt][nt][3]);
        }
    }
#undef LOADG
#undef STORES
#undef COMPUTE
}

// ---------------- row squared norms ------------------------------------------
__global__ void rowsq_kernel(const float* __restrict__ xf, float* __restrict__ sq) {
    int row = blockIdx.x, tid = threadIdx.x;
    const float* x = xf + (size_t)row * C_DIM;
    float s = 0.f;
    for (int c = tid; c < C_DIM; c += 256) { float v = x[c]; s = fmaf(v, v, s); }
    for (int off = 16; off; off >>= 1) s += __shfl_xor_sync(0xffffffffu, s, off);
    __shared__ float r[8];
    if ((tid & 31) == 0) r[tid >> 5] = s;
    __syncthreads();
    if (tid == 0) { float t = 0.f; for (int w = 0; w < 8; w++) t += r[w]; sq[row] = t; }
}

// ---------------- pairwise distance: 128x64 tile, 8x4/thread -----------------
__global__ __launch_bounds__(256) void dist_kernel(
    const float* __restrict__ xf, const float* __restrict__ sq,
    float* __restrict__ D) {
    __shared__ float As[16][128];
    __shared__ float Bs[16][64];
    const int tid  = threadIdx.x;
    const int row0 = blockIdx.y * 128;
    const int col0 = blockIdx.x * 64;
    const int am = tid >> 2, ak = (tid & 3) << 2;
    const int ty = tid >> 4, tx = tid & 15;

    float4 a0, a1, b0;
    {
        a0 = *(const float4*)(xf + (size_t)(row0 + am)      * C_DIM + ak);
        a1 = *(const float4*)(xf + (size_t)(row0 + am + 64) * C_DIM + ak);
        b0 = *(const float4*)(xf + (size_t)(col0 + am)      * C_DIM + ak);
    }
    float acc[8][4] = {};

#define D_STORE()                                                             \
    {                                                                         \
        As[ak + 0][am] = a0.x; As[ak + 1][am] = a0.y;                         \
        As[ak + 2][am] = a0.z; As[ak + 3][am] = a0.w;                         \
        As[ak + 0][am + 64] = a1.x; As[ak + 1][am + 64] = a1.y;               \
        As[ak + 2][am + 64] = a1.z; As[ak + 3][am + 64] = a1.w;               \
        if (am < 64) {                                                        \
            Bs[ak + 0][am] = b0.x; Bs[ak + 1][am] = b0.y;                     \
            Bs[ak + 2][am] = b0.z; Bs[ak + 3][am] = b0.w;                     \
        }                                                                     \
    }
#define D_COMPUTE()                                                           \
    _Pragma("unroll")                                                         \
    for (int kt = 0; kt < 16; kt++) {                                         \
        float af[8], bf[4];                                                   \
        *(float4*)&af[0] = *(const float4*)&As[kt][ty * 8];                   \
        *(float4*)&af[4] = *(const float4*)&As[kt][ty * 8 + 4];               \
        *(float4*)&bf[0] = *(const float4*)&Bs[kt][tx * 4];                   \
        _Pragma("unroll")                                                     \
        for (int i = 0; i < 8; i++)                                           \
            _Pragma("unroll")                                                 \
            for (int j = 0; j < 4; j++)                                       \
                acc[i][j] = fmaf(af[i], bf[j], acc[i][j]);                    \
    }

    D_STORE();
    __syncthreads();
    for (int k0 = 16; k0 < C_DIM; k0 += 16) {
        a0 = *(const float4*)(xf + (size_t)(row0 + am)      * C_DIM + k0 + ak);
        a1 = *(const float4*)(xf + (size_t)(row0 + am + 64) * C_DIM + k0 + ak);
        b0 = *(const float4*)(xf + (size_t)(col0 + am)      * C_DIM + k0 + ak);
        D_COMPUTE();
        __syncthreads();
        D_STORE();
        __syncthreads();
    }
    D_COMPUTE();

#pragma unroll
    for (int i = 0; i < 8; i++) {
        int r = row0 + ty * 8 + i;
        float sqr = sq[r];
        float4 o;
        int c = col0 + tx * 4;
        o.x = sqrtf(fmaxf(sqr + sq[c + 0] - 2.f * acc[i][0], 0.f));
        o.y = sqrtf(fmaxf(sqr + sq[c + 1] - 2.f * acc[i][1], 0.f));
        o.z = sqrtf(fmaxf(sqr + sq[c + 2] - 2.f * acc[i][2], 0.f));
        o.w = sqrtf(fmaxf(sqr + sq[c + 3] - 2.f * acc[i][3], 0.f));
        *(float4*)(D + (size_t)r * N_NODES + c) = o;
    }
#undef D_STORE
#undef D_COMPUTE
}

// ---------------- kNN: 8 smallest per row (diag excluded), redux merge -------
__global__ void knn_kernel(const float* __restrict__ D, int* __restrict__ neigh) {
    int gw = (blockIdx.x * blockDim.x + threadIdx.x) >> 5;
    int lane = threadIdx.x & 31;
    if (gw >= N_NODES) return;
    const float* row = D + (size_t)gw * N_NODES;
    float val[8]; int idx[8];
#pragma unroll
    for (int r = 0; r < 8; r++) { val[r] = __int_as_float(0x7f800000); idx[r] = 0; }
    for (int j = lane; j < N_NODES; j += 32) {
        if (j == gw) continue;
        float v = row[j];
        if (v < val[7]) {
            val[7] = v; idx[7] = j;
#pragma unroll
            for (int p = 7; p > 0; p--) {
                if (val[p] < val[p - 1]) {
                    float tv = val[p]; val[p] = val[p - 1]; val[p - 1] = tv;
                    int   ti = idx[p]; idx[p] = idx[p - 1]; idx[p - 1] = ti;
                }
            }
        }
    }
    int ptr = 0;
#pragma unroll
    for (int r = 0; r < 8; r++) {
        unsigned vb = (ptr < 8) ? __float_as_uint(val[ptr]) : 0x7f800000u;
        unsigned vm = __reduce_min_sync(0xffffffffu, vb);
        unsigned mi = (ptr < 8 && vb == vm) ? (unsigned)idx[ptr] : 0x7fffffffu;
        unsigned im = __reduce_min_sync(0xffffffffu, mi);
        if (lane == 0) neigh[gw * KNB + r] = (int)im;
        if (ptr < 8 && vb == vm && (unsigned)idx[ptr] == im) ptr++;
    }
}

// ---------------- sequential k-means: single warp, interleaved ownership -----
// lane l owns global indices i = j*32 + l  (j = 0..31)  → all smem accesses are
// scalar 4B at bank l: conflict-free. Global D loads coalesce per j.
__global__ void kmeans_kernel(const float* __restrict__ D, const int* __restrict__ perm,
                              int* __restrict__ assign_out) {
    __shared__ float S[KC * N_NODES];
    __shared__ float Drow_sh[N_NODES];
    __shared__ int   sperm[N_NODES];
    const int lane = threadIdx.x;
    const float INF = __int_as_float(0x7f800000);
    const unsigned FULL = 0xffffffffu;

    for (int i = lane; i < N_NODES; i += 32) sperm[i] = perm[i];
    __syncwarp();
    int mycent = (lane < KC) ? sperm[lane] : 0;
    for (int c = 0; c < KC; c++) {
        const float* row = D + (size_t)sperm[c] * N_NODES;
#pragma unroll
        for (int j = 0; j < 32; j++)
            S[c * N_NODES + j * 32 + lane] = row[j * 32 + lane];
    }
    // membership nibbles: slot j (global i = j*32+lane), value = cluster+1
    unsigned nib[4] = {0u, 0u, 0u, 0u};
    for (int c = 0; c < KC; c++) {
        int p = sperm[c];
        if ((p & 31) == lane) {
            int slot = p >> 5;
            nib[slot >> 3] |= (unsigned)(c + 1) << ((slot & 7) * 4);
        }
    }
    float cur[32];
    {
        const float* row = D + (size_t)sperm[KC] * N_NODES;
#pragma unroll
        for (int j = 0; j < 32; j++) {
            cur[j] = row[j * 32 + lane];
            Drow_sh[j * 32 + lane] = cur[j];
        }
    }
    __syncwarp();

    for (int step = 0; step < NSTEPS; step++) {
        const int ni = sperm[KC + step];
        // prefetch next node's D row (coalesced scalar loads)
        float nxt[32];
        {
            const int nn = sperm[KC + ((step + 1 < NSTEPS) ? step + 1 : step)];
            const float* row = D + (size_t)nn * N_NODES;
#pragma unroll
            for (int j = 0; j < 32; j++) nxt[j] = row[j * 32 + lane];
        }
        // nearest centroid (first-index tiebreak: lane order == centroid order)
        unsigned cb = (lane < KC) ? __float_as_uint(Drow_sh[mycent]) : 0x7f800000u;
        unsigned cm = __reduce_min_sync(FULL, cb);
        unsigned cmask = __ballot_sync(FULL, cb == cm);
        const int c = __ffs(cmask) - 1;
        const unsigned tgt = (unsigned)(c + 1);
        // S[c] += Drow; masked min (argmin of S over members == argmin of mean)
        float* Sc = S + c * N_NODES;
        float vv[32];
#pragma unroll
        for (int j = 0; j < 32; j++) {
            float s = Sc[j * 32 + lane] + cur[j];
            Sc[j * 32 + lane] = s;
            bool memb = (((nib[j >> 3] >> ((j & 7) * 4)) & 15u) == tgt)
                        | ((j * 32 + lane) == ni);
            vv[j] = memb ? s : INF;
        }
        // in-lane tree min (depth 5), then equality mask for smallest j
        float tm[16];
#pragma unroll
        for (int t = 0; t < 16; t++) tm[t] = fminf(vv[t], vv[t + 16]);
#pragma unroll
        for (int t = 0; t < 8; t++)  tm[t] = fminf(tm[t], tm[t + 8]);
#pragma unroll
        for (int t = 0; t < 4; t++)  tm[t] = fminf(tm[t], tm[t + 4]);
        tm[0] = fminf(tm[0], tm[2]); tm[1] = fminf(tm[1], tm[3]);
        const float minv = fminf(tm[0], tm[1]);
        unsigned msk = 0u;
#pragma unroll
        for (int j = 0; j < 32; j++) msk |= (vv[j] == minv) ? (1u << j) : 0u;
        const int besti = (__ffs(msk) - 1) * 32 + lane;   // smallest global i in lane
        // cross-lane: min value, then min global index among tied lanes
        unsigned bb = __float_as_uint(minv);
        unsigned bm = __reduce_min_sync(FULL, bb);
        unsigned cand = (bb == bm) ? (unsigned)besti : 0xffffffffu;
        unsigned newc = __reduce_min_sync(FULL, cand);
        if (lane == c) mycent = (int)newc;
        // record assignment of ni
        if ((ni & 31) == lane) {
            int slot = ni >> 5;
            nib[slot >> 3] |= tgt << ((slot & 7) * 4);
        }
        // rotate prefetched row into place
#pragma unroll
        for (int j = 0; j < 32; j++) {
            Drow_sh[j * 32 + lane] = nxt[j];
            cur[j] = nxt[j];
        }
        __syncwarp();
    }
#pragma unroll
    for (int j = 0; j < 32; j++)
        assign_out[j * 32 + lane] =
            (int)((nib[j >> 3] >> ((j & 7) * 4)) & 15u) - 1;
}

// ---------------- E[e] = sum_{v in neigh(e)} xf[v] ---------------------------
__global__ void agg_local_kernel(const float* __restrict__ xf, const int* __restrict__ neigh,
                                 float* __restrict__ E) {
    int e = blockIdx.x;
    int nb[KNB];
#pragma unroll
    for (int j = 0; j < KNB; j++) nb[j] = neigh[e * KNB + j];
    for (int c = threadIdx.x; c < C_DIM; c += 256) {
        float s = 0.f;
#pragma unroll
        for (int j = 0; j < KNB; j++) s += xf[(size_t)nb[j] * C_DIM + c];
        E[(size_t)e * C_DIM + c] = s;
    }
}

// ---------------- E[n+c] = sum_{assign[v]==c} xf[v] --------------------------
__global__ void agg_global_kernel(const float* __restrict__ xf, const int* __restrict__ assign_,
                                  float* __restrict__ E) {
    __shared__ int sa[N_NODES];
    int tid = threadIdx.x;
    for (int i = tid; i < N_NODES; i += 256) sa[i] = assign_[i];
    __syncthreads();
    int c = blockIdx.x;
    int col = blockIdx.y * 256 + tid;
    float s = 0.f;
    for (int i = 0; i < N_NODES; i++)
        if (sa[i] == c) s += xf[(size_t)i * C_DIM + col];
    E[(size_t)(N_NODES + c) * C_DIM + col] = s;
}

// ---------------- Y[v] = sum_{e: v in neigh(e)} X1[e] + X1[n+assign[v]] ------
__global__ void agg_out_kernel(const float* __restrict__ X1, const int* __restrict__ neigh,
                               const int* __restrict__ assign_, float* __restrict__ Y) {
    int v = blockIdx.x;
    __shared__ int list[N_NODES];
    __shared__ int cnt_s;
    int tid = threadIdx.x, lane = tid & 31, wid = tid >> 5;
    if (wid == 0) {
        int cnt = 0;
        for (int base = 0; base < N_NODES; base += 32) {
            int e = base + lane;
            const int4* p = (const int4*)(neigh + e * KNB);
            int4 q0 = p[0], q1 = p[1];
            bool m = (q0.x == v) | (q0.y == v) | (q0.z == v) | (q0.w == v) |
                     (q1.x == v) | (q1.y == v) | (q1.z == v) | (q1.w == v);
            unsigned msk = __ballot_sync(0xffffffffu, m);
            if (m) list[cnt + __popc(msk & ((1u << lane) - 1u))] = e;
            cnt += __popc(msk);
        }
        if (lane == 0) cnt_s = cnt;
    }
    __syncthreads();
    int cnt = cnt_s;
    int ge = N_NODES + assign_[v];
    float s[8];
#pragma unroll
    for (int w = 0; w < 8; w++) s[w] = X1[(size_t)ge * C_DIM + tid + w * 256];
    for (int t = 0; t < cnt; t++) {
        const float* xr = X1 + (size_t)list[t] * C_DIM;
#pragma unroll
        for (int w = 0; w < 8; w++) s[w] += xr[tid + w * 256];
    }
#pragma unroll
    for (int w = 0; w < 8; w++) Y[(size_t)v * C_DIM + tid + w * 256] = s[w];
}

// ---------------- host launcher ----------------------------------------------
extern "C" void kernel_launch(void* const* d_in, const int* in_sizes, int n_in,
                              void* d_out, int out_size) {
    const float* x0  = (const float*)d_in[0];
    const float* wfc = (const float*)d_in[1];
    const float* bfc = (const float*)d_in[2];
    const float* w1  = (const float*)d_in[3];
    const float* w2  = (const float*)d_in[4];
    float* out = (float*)d_out;

    float *xf, *sq, *D, *E, *X1, *Y;
    int *neigh, *perm, *assign_;
    cudaGetSymbolAddress((void**)&xf,      g_xf);
    cudaGetSymbolAddress((void**)&sq,      g_sq);
    cudaGetSymbolAddress((void**)&D,       g_D);
    cudaGetSymbolAddress((void**)&neigh,   g_neigh);
    cudaGetSymbolAddress((void**)&perm,    g_perm);
    cudaGetSymbolAddress((void**)&assign_, g_assign);
    cudaGetSymbolAddress((void**)&E,       g_E);
    cudaGetSymbolAddress((void**)&X1,      g_X1);
    cudaGetSymbolAddress((void**)&Y,       g_Y);

    const size_t dynsmem = (2 * AS_STAGE + 2 * BS_STAGE) * sizeof(float);  // 69632
    cudaFuncSetAttribute(mma_gemm_kernel,
                         cudaFuncAttributeMaxDynamicSharedMemorySize, (int)dynsmem);

    perm_kernel<<<1, 1024>>>(perm);
    sgemm_kernel<<<dim3(C_DIM / 128, N_NODES / 128), 256>>>(x0, wfc, bfc, xf,
                                                            N_NODES, C_DIM, C_DIM);
    rowsq_kernel<<<N_NODES, 256>>>(xf, sq);
    dist_kernel<<<dim3(N_NODES / 64, N_NODES / 128), 256>>>(xf, sq, D);
    knn_kernel<<<N_NODES / 8, 256>>>(D, neigh);
    kmeans_kernel<<<1, 32>>>(D, perm, assign_);
    agg_local_kernel<<<N_NODES, 256>>>(xf, neigh, E);
    agg_global_kernel<<<dim3(KC, C_DIM / 256), 256>>>(xf, assign_, E);
    mma_gemm_kernel<<<dim3(C_DIM / 128, E_PAD / 128), 256, dynsmem>>>(E, w1, X1);
    agg_out_kernel<<<N_NODES, 256>>>(X1, neigh, assign_, Y);
    mma_gemm_kernel<<<dim3(C_DIM / 128, N_NODES / 128), 256, dynsmem>>>(Y, w2, out);
}

// round 6
// speedup vs baseline: 2.0248x; 1.2674x over previous
#include <cuda_runtime.h>
#include <cstdint>
#include <cstddef>

#define N_NODES 1024
#define C_DIM   2048
#define KNB     8
#define KC      8
#define N_EDGES (N_NODES + KC)
#define NSTEPS  (N_NODES - KC)
#define E_PAD   1152   // padded edge-row count (9 * 128)

typedef unsigned long long u64;

// ---------------- scratch (static __device__, zero-initialized) --------------
__device__ float g_xf[N_NODES * C_DIM];
__device__ float g_sq[N_NODES];
__device__ float g_D[N_NODES * N_NODES];
__device__ int   g_neigh[N_NODES * KNB];
__device__ int   g_perm[N_NODES];
__device__ int   g_assign[N_NODES];
__device__ float g_E[E_PAD * C_DIM];    // rows 1032..1151 stay zero
__device__ float g_X1[E_PAD * C_DIM];
__device__ float g_Y[N_NODES * C_DIM];

// ---------------- helpers ----------------------------------------------------
__device__ __forceinline__ float to_tf32(float x) {
    uint32_t r;
    asm("cvt.rna.tf32.f32 %0, %1;" : "=r"(r) : "f"(x));
    return __uint_as_float(r);
}

#define MMA_TF32(d, a, b)                                                     \
    asm volatile(                                                             \
        "mma.sync.aligned.m16n8k8.row.col.f32.tf32.tf32.f32 "                 \
        "{%0,%1,%2,%3}, {%4,%5,%6,%7}, {%8,%9}, {%0,%1,%2,%3};"               \
        : "+f"((d)[0]), "+f"((d)[1]), "+f"((d)[2]), "+f"((d)[3])              \
        : "r"((a)[0]), "r"((a)[1]), "r"((a)[2]), "r"((a)[3]),                 \
          "r"((b)[0]), "r"((b)[1]))

// ---------------- threefry-2x32 (20 rounds) ----------------------------------
__device__ __forceinline__ void threefry2x32(unsigned k0, unsigned k1,
                                             unsigned& x0, unsigned& x1) {
    unsigned ks2 = k0 ^ k1 ^ 0x1BD11BDAu;
    x0 += k0; x1 += k1;
#define TF_R(r) { x0 += x1; x1 = (x1 << (r)) | (x1 >> (32 - (r))); x1 ^= x0; }
    TF_R(13) TF_R(15) TF_R(26) TF_R(6)
    x0 += k1;  x1 += ks2 + 1u;
    TF_R(17) TF_R(29) TF_R(16) TF_R(24)
    x0 += ks2; x1 += k0 + 2u;
    TF_R(13) TF_R(15) TF_R(26) TF_R(6)
    x0 += k0;  x1 += k1 + 3u;
    TF_R(17) TF_R(29) TF_R(16) TF_R(24)
    x0 += k1;  x1 += ks2 + 4u;
    TF_R(13) TF_R(15) TF_R(26) TF_R(6)
    x0 += ks2; x1 += k0 + 5u;
#undef TF_R
}

__global__ void perm_kernel(int* __restrict__ perm) {
    __shared__ u64 keys[N_NODES];
    int tid = threadIdx.x;
    unsigned s0, s1;
    { unsigned a0 = 0u, a1 = 1u; threefry2x32(0u, 42u, a0, a1); s0 = a0; s1 = a1; }
    if (tid < 512) {
        unsigned x0 = 0u, x1 = (unsigned)tid;
        threefry2x32(s0, s1, x0, x1);
        keys[tid] = ((u64)(x0 ^ x1) << 32) | (unsigned)tid;
        unsigned y0 = 0u, y1 = (unsigned)(tid + 512);
        threefry2x32(s0, s1, y0, y1);
        keys[tid + 512] = ((u64)(y0 ^ y1) << 32) | (unsigned)(tid + 512);
    }
    __syncthreads();
    for (int k = 2; k <= N_NODES; k <<= 1) {
        for (int j = k >> 1; j > 0; j >>= 1) {
            int ixj = tid ^ j;
            if (ixj > tid) {
                u64 a = keys[tid], b = keys[ixj];
                bool up = ((tid & k) == 0);
                if ((a > b) == up) { keys[tid] = b; keys[ixj] = a; }
            }
            __syncthreads();
        }
    }
    perm[tid] = (int)(keys[tid] & 0xffffffffull);
}

// ---------------- fp32 SGEMM (GEMM1 only): 128x128, 8x8/thread ---------------
__global__ __launch_bounds__(256) void sgemm_kernel(
    const float* __restrict__ A, const float* __restrict__ B,
    const float* __restrict__ bias, float* __restrict__ C,
    int M, int N, int K) {
    __shared__ float As[16][128];
    __shared__ float Bs[16][128];
    const int tid  = threadIdx.x;
    const int row0 = blockIdx.y * 128;
    const int col0 = blockIdx.x * 128;
    const int am = tid >> 2, ak = (tid & 3) << 2;
    const int bk = tid >> 5, bn = (tid & 31) << 2;
    const int ty = tid >> 4, tx = tid & 15;
    const float4 z4 = make_float4(0.f, 0.f, 0.f, 0.f);

    float4 a0, a1, b0, b1;
    {
        int r = row0 + am;
        a0 = (r      < M) ? *(const float4*)(A + (size_t)r        * K + ak) : z4;
        a1 = (r + 64 < M) ? *(const float4*)(A + (size_t)(r + 64) * K + ak) : z4;
        b0 = *(const float4*)(B + (size_t)bk       * N + col0 + bn);
        b1 = *(const float4*)(B + (size_t)(bk + 8) * N + col0 + bn);
    }
    float acc[8][8] = {};

#define STORE_TILES()                                                         \
    {                                                                         \
        As[ak + 0][am] = a0.x; As[ak + 1][am] = a0.y;                         \
        As[ak + 2][am] = a0.z; As[ak + 3][am] = a0.w;                         \
        As[ak + 0][am + 64] = a1.x; As[ak + 1][am + 64] = a1.y;               \
        As[ak + 2][am + 64] = a1.z; As[ak + 3][am + 64] = a1.w;               \
        *(float4*)&Bs[bk][bn]     = b0;                                       \
        *(float4*)&Bs[bk + 8][bn] = b1;                                       \
    }
#define COMPUTE_TILE()                                                        \
    _Pragma("unroll")                                                         \
    for (int kt = 0; kt < 16; kt++) {                                         \
        float af[8], bf[8];                                                   \
        *(float4*)&af[0] = *(const float4*)&As[kt][ty * 8];                   \
        *(float4*)&af[4] = *(const float4*)&As[kt][ty * 8 + 4];               \
        *(float4*)&bf[0] = *(const float4*)&Bs[kt][tx * 8];                   \
        *(float4*)&bf[4] = *(const float4*)&Bs[kt][tx * 8 + 4];               \
        _Pragma("unroll")                                                     \
        for (int i = 0; i < 8; i++)                                           \
            _Pragma("unroll")                                                 \
            for (int j = 0; j < 8; j++)                                       \
                acc[i][j] = fmaf(af[i], bf[j], acc[i][j]);                    \
    }

    STORE_TILES();
    __syncthreads();
    for (int k0 = 16; k0 < K; k0 += 16) {
        int r = row0 + am;
        a0 = (r      < M) ? *(const float4*)(A + (size_t)r        * K + k0 + ak) : z4;
        a1 = (r + 64 < M) ? *(const float4*)(A + (size_t)(r + 64) * K + k0 + ak) : z4;
        b0 = *(const float4*)(B + (size_t)(k0 + bk)     * N + col0 + bn);
        b1 = *(const float4*)(B + (size_t)(k0 + bk + 8) * N + col0 + bn);
        COMPUTE_TILE();
        __syncthreads();
        STORE_TILES();
        __syncthreads();
    }
    COMPUTE_TILE();

    float4 bias0 = z4, bias1 = z4;
    if (bias) {
        bias0 = *(const float4*)(bias + col0 + tx * 8);
        bias1 = *(const float4*)(bias + col0 + tx * 8 + 4);
    }
#pragma unroll
    for (int i = 0; i < 8; i++) {
        int r = row0 + ty * 8 + i;
        if (r < M) {
            float4 o0 = make_float4(acc[i][0] + bias0.x, acc[i][1] + bias0.y,
                                    acc[i][2] + bias0.z, acc[i][3] + bias0.w);
            float4 o1 = make_float4(acc[i][4] + bias1.x, acc[i][5] + bias1.y,
                                    acc[i][6] + bias1.z, acc[i][7] + bias1.w);
            *(float4*)(C + (size_t)r * N + col0 + tx * 8)     = o0;
            *(float4*)(C + (size_t)r * N + col0 + tx * 8 + 4) = o1;
        }
    }
#undef STORE_TILES
#undef COMPUTE_TILE
}

// ---------------- tf32 mma.sync GEMM: C[M,2048] = A[M,2048] @ B[2048,2048] ---
#define AS_STRIDE 36
#define AS_STAGE  (128 * AS_STRIDE)
#define BS_STAGE  (32 * 128)

__global__ __launch_bounds__(256) void mma_gemm_kernel(
    const float* __restrict__ A, const float* __restrict__ B,
    float* __restrict__ C) {
    extern __shared__ float sm[];
    float* As = sm;                    // [2][128][36]
    float* Bs = sm + 2 * AS_STAGE;     // [2][32][128]
    const int tid  = threadIdx.x;
    const int lane = tid & 31, wid = tid >> 5;
    const int warp_m = wid >> 2, warp_n = wid & 3;
    const int g = lane >> 2, tig = lane & 3;
    const int row0 = blockIdx.y * 128, col0 = blockIdx.x * 128;

    float acc[4][4][4] = {};
    float4 ar[4], br[4];

#define LOADG(ks)                                                             \
    _Pragma("unroll")                                                         \
    for (int i = 0; i < 4; i++) {                                             \
        int ch = tid * 4 + i;                                                 \
        ar[i] = *(const float4*)(A + (size_t)(row0 + (ch >> 3)) * C_DIM       \
                                 + (ks) * 32 + (ch & 7) * 4);                 \
        br[i] = *(const float4*)(B + (size_t)((ks) * 32 + (ch >> 5)) * C_DIM  \
                                 + col0 + (ch & 31) * 4);                     \
    }

#define STORES(buf)                                                           \
    {                                                                         \
        float* Ab = As + (buf) * AS_STAGE;                                    \
        float* Bb = Bs + (buf) * BS_STAGE;                                    \
        _Pragma("unroll")                                                     \
        for (int i = 0; i < 4; i++) {                                         \
            int ch = tid * 4 + i;                                             \
            float4 v = ar[i];                                                 \
            v.x = to_tf32(v.x); v.y = to_tf32(v.y);                           \
            v.z = to_tf32(v.z); v.w = to_tf32(v.w);                           \
            *(float4*)(Ab + (ch >> 3) * AS_STRIDE + (ch & 7) * 4) = v;        \
            float4 w = br[i];                                                 \
            w.x = to_tf32(w.x); w.y = to_tf32(w.y);                           \
            w.z = to_tf32(w.z); w.w = to_tf32(w.w);                           \
            int kb = ch >> 5, n4 = ch & 31;                                   \
            *(float4*)(Bb + kb * 128 + ((n4 * 4) ^ ((kb & 3) << 3))) = w;     \
        }                                                                     \
    }

#define COMPUTE(buf)                                                          \
    {                                                                         \
        const float* Ab = As + (buf) * AS_STAGE;                              \
        const float* Bb = Bs + (buf) * BS_STAGE;                              \
        _Pragma("unroll")                                                     \
        for (int kk = 0; kk < 4; kk++) {                                      \
            uint32_t af[4][4], bf[4][2];                                      \
            const int k1 = kk * 8 + tig, k2 = kk * 8 + tig + 4;               \
            _Pragma("unroll")                                                 \
            for (int mt = 0; mt < 4; mt++) {                                  \
                int m0 = warp_m * 64 + mt * 16;                               \
                af[mt][0] = __float_as_uint(Ab[(m0 + g)     * AS_STRIDE + k1]); \
                af[mt][1] = __float_as_uint(Ab[(m0 + 8 + g) * AS_STRIDE + k1]); \
                af[mt][2] = __float_as_uint(Ab[(m0 + g)     * AS_STRIDE + k2]); \
                af[mt][3] = __float_as_uint(Ab[(m0 + 8 + g) * AS_STRIDE + k2]); \
            }                                                                 \
            _Pragma("unroll")                                                 \
            for (int nt = 0; nt < 4; nt++) {                                  \
                int n0 = warp_n * 32 + nt * 8;                                \
                bf[nt][0] = __float_as_uint(Bb[k1 * 128 + ((n0 + g) ^ (tig << 3))]); \
                bf[nt][1] = __float_as_uint(Bb[k2 * 128 + ((n0 + g) ^ (tig << 3))]); \
            }                                                                 \
            _Pragma("unroll")                                                 \
            for (int mt = 0; mt < 4; mt++)                                    \
                _Pragma("unroll")                                             \
                for (int nt = 0; nt < 4; nt++)                                \
                    MMA_TF32(acc[mt][nt], af[mt], bf[nt]);                    \
        }                                                                     \
    }

    LOADG(0);
    STORES(0);
    __syncthreads();
    for (int ks = 0; ks < 64; ks++) {
        const int cur = ks & 1;
        if (ks < 63) { LOADG(ks + 1); }
        COMPUTE(cur);
        if (ks < 63) { STORES(cur ^ 1); }
        __syncthreads();
    }

#pragma unroll
    for (int mt = 0; mt < 4; mt++) {
#pragma unroll
        for (int nt = 0; nt < 4; nt++) {
            int r  = row0 + warp_m * 64 + mt * 16 + g;
            int cc = col0 + warp_n * 32 + nt * 8 + tig * 2;
            *(float2*)(C + (size_t)r * C_DIM + cc) =
                make_float2(acc[mt][nt][0], acc[mt][nt][1]);
            *(float2*)(C + (size_t)(r + 8) * C_DIM + cc) =
                make_float2(acc[mt][nt][2], acc[mt][nt][3]);
        }
    }
#undef LOADG
#undef STORES
#undef COMPUTE
}

// ---------------- row squared norms ------------------------------------------
__global__ void rowsq_kernel(const float* __restrict__ xf, float* __restrict__ sq) {
    int row = blockIdx.x, tid = threadIdx.x;
    const float* x = xf + (size_t)row * C_DIM;
    float s = 0.f;
    for (int c = tid; c < C_DIM; c += 256) { float v = x[c]; s = fmaf(v, v, s); }
    for (int off = 16; off; off >>= 1) s += __shfl_xor_sync(0xffffffffu, s, off);
    __shared__ float r[8];
    if ((tid & 31) == 0) r[tid >> 5] = s;
    __syncthreads();
    if (tid == 0) { float t = 0.f; for (int w = 0; w < 8; w++) t += r[w]; sq[row] = t; }
}

// ---------------- pairwise distance: 128x64 tile, 8x4/thread -----------------
__global__ __launch_bounds__(256) void dist_kernel(
    const float* __restrict__ xf, const float* __restrict__ sq,
    float* __restrict__ D) {
    __shared__ float As[16][128];
    __shared__ float Bs[16][64];
    const int tid  = threadIdx.x;
    const int row0 = blockIdx.y * 128;
    const int col0 = blockIdx.x * 64;
    const int am = tid >> 2, ak = (tid & 3) << 2;
    const int ty = tid >> 4, tx = tid & 15;

    float4 a0, a1, b0;
    {
        a0 = *(const float4*)(xf + (size_t)(row0 + am)      * C_DIM + ak);
        a1 = *(const float4*)(xf + (size_t)(row0 + am + 64) * C_DIM + ak);
        b0 = *(const float4*)(xf + (size_t)(col0 + am)      * C_DIM + ak);
    }
    float acc[8][4] = {};

#define D_STORE()                                                             \
    {                                                                         \
        As[ak + 0][am] = a0.x; As[ak + 1][am] = a0.y;                         \
        As[ak + 2][am] = a0.z; As[ak + 3][am] = a0.w;                         \
        As[ak + 0][am + 64] = a1.x; As[ak + 1][am + 64] = a1.y;               \
        As[ak + 2][am + 64] = a1.z; As[ak + 3][am + 64] = a1.w;               \
        if (am < 64) {                                                        \
            Bs[ak + 0][am] = b0.x; Bs[ak + 1][am] = b0.y;                     \
            Bs[ak + 2][am] = b0.z; Bs[ak + 3][am] = b0.w;                     \
        }                                                                     \
    }
#define D_COMPUTE()                                                           \
    _Pragma("unroll")                                                         \
    for (int kt = 0; kt < 16; kt++) {                                         \
        float af[8], bf[4];                                                   \
        *(float4*)&af[0] = *(const float4*)&As[kt][ty * 8];                   \
        *(float4*)&af[4] = *(const float4*)&As[kt][ty * 8 + 4];               \
        *(float4*)&bf[0] = *(const float4*)&Bs[kt][tx * 4];                   \
        _Pragma("unroll")                                                     \
        for (int i = 0; i < 8; i++)                                           \
            _Pragma("unroll")                                                 \
            for (int j = 0; j < 4; j++)                                       \
                acc[i][j] = fmaf(af[i], bf[j], acc[i][j]);                    \
    }

    D_STORE();
    __syncthreads();
    for (int k0 = 16; k0 < C_DIM; k0 += 16) {
        a0 = *(const float4*)(xf + (size_t)(row0 + am)      * C_DIM + k0 + ak);
        a1 = *(const float4*)(xf + (size_t)(row0 + am + 64) * C_DIM + k0 + ak);
        b0 = *(const float4*)(xf + (size_t)(col0 + am)      * C_DIM + k0 + ak);
        D_COMPUTE();
        __syncthreads();
        D_STORE();
        __syncthreads();
    }
    D_COMPUTE();

#pragma unroll
    for (int i = 0; i < 8; i++) {
        int r = row0 + ty * 8 + i;
        float sqr = sq[r];
        float4 o;
        int c = col0 + tx * 4;
        o.x = sqrtf(fmaxf(sqr + sq[c + 0] - 2.f * acc[i][0], 0.f));
        o.y = sqrtf(fmaxf(sqr + sq[c + 1] - 2.f * acc[i][1], 0.f));
        o.z = sqrtf(fmaxf(sqr + sq[c + 2] - 2.f * acc[i][2], 0.f));
        o.w = sqrtf(fmaxf(sqr + sq[c + 3] - 2.f * acc[i][3], 0.f));
        *(float4*)(D + (size_t)r * N_NODES + c) = o;
    }
#undef D_STORE
#undef D_COMPUTE
}

// ---------------- kNN: 8 smallest per row (diag excluded), redux merge -------
__global__ void knn_kernel(const float* __restrict__ D, int* __restrict__ neigh) {
    int gw = (blockIdx.x * blockDim.x + threadIdx.x) >> 5;
    int lane = threadIdx.x & 31;
    if (gw >= N_NODES) return;
    const float* row = D + (size_t)gw * N_NODES;
    float val[8]; int idx[8];
#pragma unroll
    for (int r = 0; r < 8; r++) { val[r] = __int_as_float(0x7f800000); idx[r] = 0; }
    for (int j = lane; j < N_NODES; j += 32) {
        if (j == gw) continue;
        float v = row[j];
        if (v < val[7]) {
            val[7] = v; idx[7] = j;
#pragma unroll
            for (int p = 7; p > 0; p--) {
                if (val[p] < val[p - 1]) {
                    float tv = val[p]; val[p] = val[p - 1]; val[p - 1] = tv;
                    int   ti = idx[p]; idx[p] = idx[p - 1]; idx[p - 1] = ti;
                }
            }
        }
    }
    int ptr = 0;
#pragma unroll
    for (int r = 0; r < 8; r++) {
        unsigned vb = (ptr < 8) ? __float_as_uint(val[ptr]) : 0x7f800000u;
        unsigned vm = __reduce_min_sync(0xffffffffu, vb);
        unsigned mi = (ptr < 8 && vb == vm) ? (unsigned)idx[ptr] : 0x7fffffffu;
        unsigned im = __reduce_min_sync(0xffffffffu, mi);
        if (lane == 0) neigh[gw * KNB + r] = (int)im;
        if (ptr < 8 && vb == vm && (unsigned)idx[ptr] == im) ptr++;
    }
}

// ---------------- sequential k-means: 4 warps, 2 barriers/step ---------------
// thread t owns global indices i = j*128 + t (j = 0..7). S rows are touched only
// by their owner thread -> no barrier needed for S. Warp 0 owns centroid state.
__global__ __launch_bounds__(128) void kmeans_kernel(
    const float* __restrict__ D, const int* __restrict__ perm,
    int* __restrict__ assign_out) {
    __shared__ float S[KC * N_NODES];       // 32KB
    __shared__ float Drow_sh[N_NODES];      // 4KB
    __shared__ int   sperm[N_NODES];        // 4KB
    __shared__ u64   red[4];
    __shared__ int   cur_c_sh;
    const int t = threadIdx.x;
    const int lane = t & 31, wid = t >> 5;
    const float INF = __int_as_float(0x7f800000);
    const unsigned FULL = 0xffffffffu;

    for (int i = t; i < N_NODES; i += 128) sperm[i] = perm[i];
    __syncthreads();
    int mycent = (wid == 0 && lane < KC) ? sperm[lane] : 0;
    for (int c = 0; c < KC; c++) {
        const float* row = D + (size_t)sperm[c] * N_NODES;
#pragma unroll
        for (int j = 0; j < 8; j++)
            S[c * N_NODES + j * 128 + t] = row[j * 128 + t];
    }
    // membership nibbles: slot j (global i = j*128+t), value = cluster+1
    unsigned nib = 0u;
    for (int c = 0; c < KC; c++) {
        int p = sperm[c];
        if ((p & 127) == t) nib |= (unsigned)(c + 1) << ((p >> 7) * 4);
    }
    float cur[8];
    {
        const float* row = D + (size_t)sperm[KC] * N_NODES;
#pragma unroll
        for (int j = 0; j < 8; j++) {
            cur[j] = row[j * 128 + t];
            Drow_sh[j * 128 + t] = cur[j];
        }
    }
    int c_prev = -1;   // warp0-uniform
    __syncthreads();

    for (int step = 0; step < NSTEPS; step++) {
        const int ni = sperm[KC + step];
        if (wid == 0) {
            // finalize previous step's new centroid from per-warp pairs
            if (step > 0) {
                u64 m = ~0ull;
                if (lane == 0) {
                    m = red[0];
                    if (red[1] < m) m = red[1];
                    if (red[2] < m) m = red[2];
                    if (red[3] < m) m = red[3];
                }
                unsigned newc = __shfl_sync(FULL, (unsigned)(m & 0xffffffffull), 0);
                if (lane == c_prev) mycent = (int)newc;
            }
            // nearest centroid for ni (first-index tiebreak: lane order)
            unsigned cb = (lane < KC) ? __float_as_uint(Drow_sh[mycent]) : 0x7f800000u;
            unsigned cm = __reduce_min_sync(FULL, cb);
            unsigned cmask = __ballot_sync(FULL, cb == cm);
            int c = __ffs(cmask) - 1;
            if (lane == 0) cur_c_sh = c;
            c_prev = c;
        }
        __syncthreads();   // bar A: cur_c visible
        const int c = cur_c_sh;
        const unsigned tgt = (unsigned)(c + 1);
        // prefetch next node's D row (coalesced)
        float nxt[8];
        {
            const int nn = sperm[KC + ((step + 1 < NSTEPS) ? step + 1 : step)];
            const float* row = D + (size_t)nn * N_NODES;
#pragma unroll
            for (int j = 0; j < 8; j++) nxt[j] = row[j * 128 + t];
        }
        // S[c] += Drow; masked min (argmin of S over members == argmin of mean)
        float* Sc = S + c * N_NODES;
        float vv[8];
#pragma unroll
        for (int j = 0; j < 8; j++) {
            float s = Sc[j * 128 + t] + cur[j];
            Sc[j * 128 + t] = s;
            bool memb = (((nib >> (j * 4)) & 15u) == tgt) | ((j * 128 + t) == ni);
            vv[j] = memb ? s : INF;
        }
        // in-thread tree min + smallest-j mask
        float t4[4];
#pragma unroll
        for (int q = 0; q < 4; q++) t4[q] = fminf(vv[q], vv[q + 4]);
        t4[0] = fminf(t4[0], t4[2]); t4[1] = fminf(t4[1], t4[3]);
        const float minv = fminf(t4[0], t4[1]);
        unsigned msk = 0u;
#pragma unroll
        for (int j = 0; j < 8; j++) msk |= (vv[j] == minv) ? (1u << j) : 0u;
        const int besti = (__ffs(msk) - 1) * 128 + t;
        // per-warp argmin (value, then smallest global index)
        unsigned bb = __float_as_uint(minv);
        unsigned bm = __reduce_min_sync(FULL, bb);
        unsigned cand = (bb == bm) ? (unsigned)besti : 0xffffffffu;
        unsigned im = __reduce_min_sync(FULL, cand);
        if (lane == 0) red[wid] = ((u64)bm << 32) | im;
        // record assignment of ni
        if ((ni & 127) == t) nib |= tgt << ((ni >> 7) * 4);
        // rotate prefetched row into place
#pragma unroll
        for (int j = 0; j < 8; j++) {
            Drow_sh[j * 128 + t] = nxt[j];
            cur[j] = nxt[j];
        }
        __syncthreads();   // bar B: red + Drow_sh visible for next step
    }
#pragma unroll
    for (int j = 0; j < 8; j++)
        assign_out[j * 128 + t] = (int)((nib >> (j * 4)) & 15u) - 1;
}

// ---------------- E[e] = sum_{v in neigh(e)} xf[v] ---------------------------
__global__ void agg_local_kernel(const float* __restrict__ xf, const int* __restrict__ neigh,
                                 float* __restrict__ E) {
    int e = blockIdx.x;
    int nb[KNB];
#pragma unroll
    for (int j = 0; j < KNB; j++) nb[j] = neigh[e * KNB + j];
    for (int c = threadIdx.x; c < C_DIM; c += 256) {
        float s = 0.f;
#pragma unroll
        for (int j = 0; j < KNB; j++) s += xf[(size_t)nb[j] * C_DIM + c];
        E[(size_t)e * C_DIM + c] = s;
    }
}

// ---------------- E[n+c] = sum_{assign[v]==c} xf[v] --------------------------
__global__ void agg_global_kernel(const float* __restrict__ xf, const int* __restrict__ assign_,
                                  float* __restrict__ E) {
    __shared__ int sa[N_NODES];
    int tid = threadIdx.x;
    for (int i = tid; i < N_NODES; i += 256) sa[i] = assign_[i];
    __syncthreads();
    int c = blockIdx.x;
    int col = blockIdx.y * 256 + tid;
    float s = 0.f;
    for (int i = 0; i < N_NODES; i++)
        if (sa[i] == c) s += xf[(size_t)i * C_DIM + col];
    E[(size_t)(N_NODES + c) * C_DIM + col] = s;
}

// ---------------- Y[v] = sum_{e: v in neigh(e)} X1[e] + X1[n+assign[v]] ------
__global__ void agg_out_kernel(const float* __restrict__ X1, const int* __restrict__ neigh,
                               const int* __restrict__ assign_, float* __restrict__ Y) {
    int v = blockIdx.x;
    __shared__ int list[N_NODES];
    __shared__ int cnt_s;
    int tid = threadIdx.x, lane = tid & 31, wid = tid >> 5;
    if (wid == 0) {
        int cnt = 0;
        for (int base = 0; base < N_NODES; base += 32) {
            int e = base + lane;
            const int4* p = (const int4*)(neigh + e * KNB);
            int4 q0 = p[0], q1 = p[1];
            bool m = (q0.x == v) | (q0.y == v) | (q0.z == v) | (q0.w == v) |
                     (q1.x == v) | (q1.y == v) | (q1.z == v) | (q1.w == v);
            unsigned msk = __ballot_sync(0xffffffffu, m);
            if (m) list[cnt + __popc(msk & ((1u << lane) - 1u))] = e;
            cnt += __popc(msk);
        }
        if (lane == 0) cnt_s = cnt;
    }
    __syncthreads();
    int cnt = cnt_s;
    int ge = N_NODES + assign_[v];
    float s[8];
#pragma unroll
    for (int w = 0; w < 8; w++) s[w] = X1[(size_t)ge * C_DIM + tid + w * 256];
    for (int t = 0; t < cnt; t++) {
        const float* xr = X1 + (size_t)list[t] * C_DIM;
#pragma unroll
        for (int w = 0; w < 8; w++) s[w] += xr[tid + w * 256];
    }
#pragma unroll
    for (int w = 0; w < 8; w++) Y[(size_t)v * C_DIM + tid + w * 256] = s[w];
}

// ---------------- host launcher ----------------------------------------------
extern "C" void kernel_launch(void* const* d_in, const int* in_sizes, int n_in,
                              void* d_out, int out_size) {
    const float* x0  = (const float*)d_in[0];
    const float* wfc = (const float*)d_in[1];
    const float* bfc = (const float*)d_in[2];
    const float* w1  = (const float*)d_in[3];
    const float* w2  = (const float*)d_in[4];
    float* out = (float*)d_out;

    float *xf, *sq, *D, *E, *X1, *Y;
    int *neigh, *perm, *assign_;
    cudaGetSymbolAddress((void**)&xf,      g_xf);
    cudaGetSymbolAddress((void**)&sq,      g_sq);
    cudaGetSymbolAddress((void**)&D,       g_D);
    cudaGetSymbolAddress((void**)&neigh,   g_neigh);
    cudaGetSymbolAddress((void**)&perm,    g_perm);
    cudaGetSymbolAddress((void**)&assign_, g_assign);
    cudaGetSymbolAddress((void**)&E,       g_E);
    cudaGetSymbolAddress((void**)&X1,      g_X1);
    cudaGetSymbolAddress((void**)&Y,       g_Y);

    const size_t dynsmem = (2 * AS_STAGE + 2 * BS_STAGE) * sizeof(float);  // 69632
    cudaFuncSetAttribute(mma_gemm_kernel,
                         cudaFuncAttributeMaxDynamicSharedMemorySize, (int)dynsmem);

    perm_kernel<<<1, 1024>>>(perm);
    sgemm_kernel<<<dim3(C_DIM / 128, N_NODES / 128), 256>>>(x0, wfc, bfc, xf,
                                                            N_NODES, C_DIM, C_DIM);
    rowsq_kernel<<<N_NODES, 256>>>(xf, sq);
    dist_kernel<<<dim3(N_NODES / 64, N_NODES / 128), 256>>>(xf, sq, D);
    knn_kernel<<<N_NODES / 8, 256>>>(D, neigh);
    kmeans_kernel<<<1, 128>>>(D, perm, assign_);
    agg_local_kernel<<<N_NODES, 256>>>(xf, neigh, E);
    agg_global_kernel<<<dim3(KC, C_DIM / 256), 256>>>(xf, assign_, E);
    mma_gemm_kernel<<<dim3(C_DIM / 128, E_PAD / 128), 256, dynsmem>>>(E, w1, X1);
    agg_out_kernel<<<N_NODES, 256>>>(X1, neigh, assign_, Y);
    mma_gemm_kernel<<<dim3(C_DIM / 128, N_NODES / 128), 256, dynsmem>>>(Y, w2, out);
}

// round 9
// speedup vs baseline: 2.2513x; 1.1119x over previous
#include <cuda_runtime.h>
#include <cstdint>
#include <cstddef>

#define N_NODES 1024
#define C_DIM   2048
#define KNB     8
#define KC      8
#define N_EDGES (N_NODES + KC)
#define NSTEPS  (N_NODES - KC)
#define E_PAD   1152   // padded edge-row count (9 * 128)

typedef unsigned long long u64;

// ---------------- scratch (static __device__, zero-initialized) --------------
__device__ float g_xf[N_NODES * C_DIM];
__device__ float g_sq[N_NODES];
__device__ float g_D[N_NODES * N_NODES];
__device__ int   g_neigh[N_NODES * KNB];
__device__ int   g_perm[N_NODES];
__device__ int   g_assign[N_NODES];
__device__ float g_E[E_PAD * C_DIM];    // rows 1032..1151 stay zero
__device__ float g_X1[E_PAD * C_DIM];
__device__ float g_Y[N_NODES * C_DIM];

// ---------------- helpers ----------------------------------------------------
__device__ __forceinline__ float to_tf32(float x) {
    uint32_t r;
    asm("cvt.rna.tf32.f32 %0, %1;" : "=r"(r) : "f"(x));
    return __uint_as_float(r);
}

#define MMA_TF32(d, a, b)                                                     \
    asm volatile(                                                             \
        "mma.sync.aligned.m16n8k8.row.col.f32.tf32.tf32.f32 "                 \
        "{%0,%1,%2,%3}, {%4,%5,%6,%7}, {%8,%9}, {%0,%1,%2,%3};"               \
        : "+f"((d)[0]), "+f"((d)[1]), "+f"((d)[2]), "+f"((d)[3])              \
        : "r"((a)[0]), "r"((a)[1]), "r"((a)[2]), "r"((a)[3]),                 \
          "r"((b)[0]), "r"((b)[1]))

// ---------------- threefry-2x32 (20 rounds) ----------------------------------
__device__ __forceinline__ void threefry2x32(unsigned k0, unsigned k1,
                                             unsigned& x0, unsigned& x1) {
    unsigned ks2 = k0 ^ k1 ^ 0x1BD11BDAu;
    x0 += k0; x1 += k1;
#define TF_R(r) { x0 += x1; x1 = (x1 << (r)) | (x1 >> (32 - (r))); x1 ^= x0; }
    TF_R(13) TF_R(15) TF_R(26) TF_R(6)
    x0 += k1;  x1 += ks2 + 1u;
    TF_R(17) TF_R(29) TF_R(16) TF_R(24)
    x0 += ks2; x1 += k0 + 2u;
    TF_R(13) TF_R(15) TF_R(26) TF_R(6)
    x0 += k0;  x1 += k1 + 3u;
    TF_R(17) TF_R(29) TF_R(16) TF_R(24)
    x0 += k1;  x1 += ks2 + 4u;
    TF_R(13) TF_R(15) TF_R(26) TF_R(6)
    x0 += ks2; x1 += k0 + 5u;
#undef TF_R
}

__global__ void perm_kernel(int* __restrict__ perm) {
    __shared__ u64 keys[N_NODES];
    int tid = threadIdx.x;
    unsigned s0, s1;
    { unsigned a0 = 0u, a1 = 1u; threefry2x32(0u, 42u, a0, a1); s0 = a0; s1 = a1; }
    if (tid < 512) {
        unsigned x0 = 0u, x1 = (unsigned)tid;
        threefry2x32(s0, s1, x0, x1);
        keys[tid] = ((u64)(x0 ^ x1) << 32) | (unsigned)tid;
        unsigned y0 = 0u, y1 = (unsigned)(tid + 512);
        threefry2x32(s0, s1, y0, y1);
        keys[tid + 512] = ((u64)(y0 ^ y1) << 32) | (unsigned)(tid + 512);
    }
    __syncthreads();
    for (int k = 2; k <= N_NODES; k <<= 1) {
        for (int j = k >> 1; j > 0; j >>= 1) {
            int ixj = tid ^ j;
            if (ixj > tid) {
                u64 a = keys[tid], b = keys[ixj];
                bool up = ((tid & k) == 0);
                if ((a > b) == up) { keys[tid] = b; keys[ixj] = a; }
            }
            __syncthreads();
        }
    }
    perm[tid] = (int)(keys[tid] & 0xffffffffull);
}

// ---------------- fp32 SGEMM (GEMM1 only): 128x128, 8x8/thread ---------------
__global__ __launch_bounds__(256) void sgemm_kernel(
    const float* __restrict__ A, const float* __restrict__ B,
    const float* __restrict__ bias, float* __restrict__ C,
    int M, int N, int K) {
    __shared__ float As[16][128];
    __shared__ float Bs[16][128];
    const int tid  = threadIdx.x;
    const int row0 = blockIdx.y * 128;
    const int col0 = blockIdx.x * 128;
    const int am = tid >> 2, ak = (tid & 3) << 2;
    const int bk = tid >> 5, bn = (tid & 31) << 2;
    const int ty = tid >> 4, tx = tid & 15;
    const float4 z4 = make_float4(0.f, 0.f, 0.f, 0.f);

    float4 a0, a1, b0, b1;
    {
        int r = row0 + am;
        a0 = (r      < M) ? *(const float4*)(A + (size_t)r        * K + ak) : z4;
        a1 = (r + 64 < M) ? *(const float4*)(A + (size_t)(r + 64) * K + ak) : z4;
        b0 = *(const float4*)(B + (size_t)bk       * N + col0 + bn);
        b1 = *(const float4*)(B + (size_t)(bk + 8) * N + col0 + bn);
    }
    float acc[8][8] = {};

#define STORE_TILES()                                                         \
    {                                                                         \
        As[ak + 0][am] = a0.x; As[ak + 1][am] = a0.y;                         \
        As[ak + 2][am] = a0.z; As[ak + 3][am] = a0.w;                         \
        As[ak + 0][am + 64] = a1.x; As[ak + 1][am + 64] = a1.y;               \
        As[ak + 2][am + 64] = a1.z; As[ak + 3][am + 64] = a1.w;               \
        *(float4*)&Bs[bk][bn]     = b0;                                       \
        *(float4*)&Bs[bk + 8][bn] = b1;                                       \
    }
#define COMPUTE_TILE()                                                        \
    _Pragma("unroll")                                                         \
    for (int kt = 0; kt < 16; kt++) {                                         \
        float af[8], bf[8];                                                   \
        *(float4*)&af[0] = *(const float4*)&As[kt][ty * 8];                   \
        *(float4*)&af[4] = *(const float4*)&As[kt][ty * 8 + 4];               \
        *(float4*)&bf[0] = *(const float4*)&Bs[kt][tx * 8];                   \
        *(float4*)&bf[4] = *(const float4*)&Bs[kt][tx * 8 + 4];               \
        _Pragma("unroll")                                                     \
        for (int i = 0; i < 8; i++)                                           \
            _Pragma("unroll")                                                 \
            for (int j = 0; j < 8; j++)                                       \
                acc[i][j] = fmaf(af[i], bf[j], acc[i][j]);                    \
    }

    STORE_TILES();
    __syncthreads();
    for (int k0 = 16; k0 < K; k0 += 16) {
        int r = row0 + am;
        a0 = (r      < M) ? *(const float4*)(A + (size_t)r        * K + k0 + ak) : z4;
        a1 = (r + 64 < M) ? *(const float4*)(A + (size_t)(r + 64) * K + k0 + ak) : z4;
        b0 = *(const float4*)(B + (size_t)(k0 + bk)     * N + col0 + bn);
        b1 = *(const float4*)(B + (size_t)(k0 + bk + 8) * N + col0 + bn);
        COMPUTE_TILE();
        __syncthreads();
        STORE_TILES();
        __syncthreads();
    }
    COMPUTE_TILE();

    float4 bias0 = z4, bias1 = z4;
    if (bias) {
        bias0 = *(const float4*)(bias + col0 + tx * 8);
        bias1 = *(const float4*)(bias + col0 + tx * 8 + 4);
    }
#pragma unroll
    for (int i = 0; i < 8; i++) {
        int r = row0 + ty * 8 + i;
        if (r < M) {
            float4 o0 = make_float4(acc[i][0] + bias0.x, acc[i][1] + bias0.y,
                                    acc[i][2] + bias0.z, acc[i][3] + bias0.w);
            float4 o1 = make_float4(acc[i][4] + bias1.x, acc[i][5] + bias1.y,
                                    acc[i][6] + bias1.z, acc[i][7] + bias1.w);
            *(float4*)(C + (size_t)r * N + col0 + tx * 8)     = o0;
            *(float4*)(C + (size_t)r * N + col0 + tx * 8 + 4) = o1;
        }
    }
#undef STORE_TILES
#undef COMPUTE_TILE
}

// ---------------- tf32 mma.sync GEMM: C[M,2048] = A[M,2048] @ B[2048,2048] ---
#define AS_STRIDE 36
#define AS_STAGE  (128 * AS_STRIDE)
#define BS_STAGE  (32 * 128)

__global__ __launch_bounds__(256) void mma_gemm_kernel(
    const float* __restrict__ A, const float* __restrict__ B,
    float* __restrict__ C) {
    extern __shared__ float sm[];
    float* As = sm;                    // [2][128][36]
    float* Bs = sm + 2 * AS_STAGE;     // [2][32][128]
    const int tid  = threadIdx.x;
    const int lane = tid & 31, wid = tid >> 5;
    const int warp_m = wid >> 2, warp_n = wid & 3;
    const int g = lane >> 2, tig = lane & 3;
    const int row0 = blockIdx.y * 128, col0 = blockIdx.x * 128;

    float acc[4][4][4] = {};
    float4 ar[4], br[4];

#define LOADG(ks)                                                             \
    _Pragma("unroll")                                                         \
    for (int i = 0; i < 4; i++) {                                             \
        int ch = tid * 4 + i;                                                 \
        ar[i] = *(const float4*)(A + (size_t)(row0 + (ch >> 3)) * C_DIM       \
                                 + (ks) * 32 + (ch & 7) * 4);                 \
        br[i] = *(const float4*)(B + (size_t)((ks) * 32 + (ch >> 5)) * C_DIM  \
                                 + col0 + (ch & 31) * 4);                     \
    }

#define STORES(buf)                                                           \
    {                                                                         \
        float* Ab = As + (buf) * AS_STAGE;                                    \
        float* Bb = Bs + (buf) * BS_STAGE;                                    \
        _Pragma("unroll")                                                     \
        for (int i = 0; i < 4; i++) {                                         \
            int ch = tid * 4 + i;                                             \
            float4 v = ar[i];                                                 \
            v.x = to_tf32(v.x); v.y = to_tf32(v.y);                           \
            v.z = to_tf32(v.z); v.w = to_tf32(v.w);                           \
            *(float4*)(Ab + (ch >> 3) * AS_STRIDE + (ch & 7) * 4) = v;        \
            float4 w = br[i];                                                 \
            w.x = to_tf32(w.x); w.y = to_tf32(w.y);                           \
            w.z = to_tf32(w.z); w.w = to_tf32(w.w);                           \
            int kb = ch >> 5, n4 = ch & 31;                                   \
            *(float4*)(Bb + kb * 128 + ((n4 * 4) ^ ((kb & 3) << 3))) = w;     \
        }                                                                     \
    }

#define COMPUTE(buf)                                                          \
    {                                                                         \
        const float* Ab = As + (buf) * AS_STAGE;                              \
        const float* Bb = Bs + (buf) * BS_STAGE;                              \
        _Pragma("unroll")                                                     \
        for (int kk = 0; kk < 4; kk++) {                                      \
            uint32_t af[4][4], bf[4][2];                                      \
            const int k1 = kk * 8 + tig, k2 = kk * 8 + tig + 4;               \
            _Pragma("unroll")                                                 \
            for (int mt = 0; mt < 4; mt++) {                                  \
                int m0 = warp_m * 64 + mt * 16;                               \
                af[mt][0] = __float_as_uint(Ab[(m0 + g)     * AS_STRIDE + k1]); \
                af[mt][1] = __float_as_uint(Ab[(m0 + 8 + g) * AS_STRIDE + k1]); \
                af[mt][2] = __float_as_uint(Ab[(m0 + g)     * AS_STRIDE + k2]); \
                af[mt][3] = __float_as_uint(Ab[(m0 + 8 + g) * AS_STRIDE + k2]); \
            }                                                                 \
            _Pragma("unroll")                                                 \
            for (int nt = 0; nt < 4; nt++) {                                  \
                int n0 = warp_n * 32 + nt * 8;                                \
                bf[nt][0] = __float_as_uint(Bb[k1 * 128 + ((n0 + g) ^ (tig << 3))]); \
                bf[nt][1] = __float_as_uint(Bb[k2 * 128 + ((n0 + g) ^ (tig << 3))]); \
            }                                                                 \
            _Pragma("unroll")                                                 \
            for (int mt = 0; mt < 4; mt++)                                    \
                _Pragma("unroll")                                             \
                for (int nt = 0; nt < 4; nt++)                                \
                    MMA_TF32(acc[mt][nt], af[mt], bf[nt]);                    \
        }                                                                     \
    }

    LOADG(0);
    STORES(0);
    __syncthreads();
    for (int ks = 0; ks < 64; ks++) {
        const int cur = ks & 1;
        if (ks < 63) { LOADG(ks + 1); }
        COMPUTE(cur);
        if (ks < 63) { STORES(cur ^ 1); }
        __syncthreads();
    }

#pragma unroll
    for (int mt = 0; mt < 4; mt++) {
#pragma unroll
        for (int nt = 0; nt < 4; nt++) {
            int r  = row0 + warp_m * 64 + mt * 16 + g;
            int cc = col0 + warp_n * 32 + nt * 8 + tig * 2;
            *(float2*)(C + (size_t)r * C_DIM + cc) =
                make_float2(acc[mt][nt][0], acc[mt][nt][1]);
            *(float2*)(C + (size_t)(r + 8) * C_DIM + cc) =
                make_float2(acc[mt][nt][2], acc[mt][nt][3]);
        }
    }
#undef LOADG
#undef STORES
#undef COMPUTE
}

// ---------------- row squared norms ------------------------------------------
__global__ void rowsq_kernel(const float* __restrict__ xf, float* __restrict__ sq) {
    int row = blockIdx.x, tid = threadIdx.x;
    const float* x = xf + (size_t)row * C_DIM;
    float s = 0.f;
    for (int c = tid; c < C_DIM; c += 256) { float v = x[c]; s = fmaf(v, v, s); }
    for (int off = 16; off; off >>= 1) s += __shfl_xor_sync(0xffffffffu, s, off);
    __shared__ float r[8];
    if ((tid & 31) == 0) r[tid >> 5] = s;
    __syncthreads();
    if (tid == 0) { float t = 0.f; for (int w = 0; w < 8; w++) t += r[w]; sq[row] = t; }
}

// ---------------- pairwise distance: 128x64 tile, 8x4/thread -----------------
__global__ __launch_bounds__(256) void dist_kernel(
    const float* __restrict__ xf, const float* __restrict__ sq,
    float* __restrict__ D) {
    __shared__ float As[16][128];
    __shared__ float Bs[16][64];
    const int tid  = threadIdx.x;
    const int row0 = blockIdx.y * 128;
    const int col0 = blockIdx.x * 64;
    const int am = tid >> 2, ak = (tid & 3) << 2;
    const int ty = tid >> 4, tx = tid & 15;

    float4 a0, a1, b0;
    {
        a0 = *(const float4*)(xf + (size_t)(row0 + am)      * C_DIM + ak);
        a1 = *(const float4*)(xf + (size_t)(row0 + am + 64) * C_DIM + ak);
        b0 = *(const float4*)(xf + (size_t)(col0 + am)      * C_DIM + ak);
    }
    float acc[8][4] = {};

#define D_STORE()                                                             \
    {                                                                         \
        As[ak + 0][am] = a0.x; As[ak + 1][am] = a0.y;                         \
        As[ak + 2][am] = a0.z; As[ak + 3][am] = a0.w;                         \
        As[ak + 0][am + 64] = a1.x; As[ak + 1][am + 64] = a1.y;               \
        As[ak + 2][am + 64] = a1.z; As[ak + 3][am + 64] = a1.w;               \
        if (am < 64) {                                                        \
            Bs[ak + 0][am] = b0.x; Bs[ak + 1][am] = b0.y;                     \
            Bs[ak + 2][am] = b0.z; Bs[ak + 3][am] = b0.w;                     \
        }                                                                     \
    }
#define D_COMPUTE()                                                           \
    _Pragma("unroll")                                                         \
    for (int kt = 0; kt < 16; kt++) {                                         \
        float af[8], bf[4];                                                   \
        *(float4*)&af[0] = *(const float4*)&As[kt][ty * 8];                   \
        *(float4*)&af[4] = *(const float4*)&As[kt][ty * 8 + 4];               \
        *(float4*)&bf[0] = *(const float4*)&Bs[kt][tx * 4];                   \
        _Pragma("unroll")                                                     \
        for (int i = 0; i < 8; i++)                                           \
            _Pragma("unroll")                                                 \
            for (int j = 0; j < 4; j++)                                       \
                acc[i][j] = fmaf(af[i], bf[j], acc[i][j]);                    \
    }

    D_STORE();
    __syncthreads();
    for (int k0 = 16; k0 < C_DIM; k0 += 16) {
        a0 = *(const float4*)(xf + (size_t)(row0 + am)      * C_DIM + k0 + ak);
        a1 = *(const float4*)(xf + (size_t)(row0 + am + 64) * C_DIM + k0 + ak);
        b0 = *(const float4*)(xf + (size_t)(col0 + am)      * C_DIM + k0 + ak);
        D_COMPUTE();
        __syncthreads();
        D_STORE();
        __syncthreads();
    }
    D_COMPUTE();

#pragma unroll
    for (int i = 0; i < 8; i++) {
        int r = row0 + ty * 8 + i;
        float sqr = sq[r];
        float4 o;
        int c = col0 + tx * 4;
        o.x = sqrtf(fmaxf(sqr + sq[c + 0] - 2.f * acc[i][0], 0.f));
        o.y = sqrtf(fmaxf(sqr + sq[c + 1] - 2.f * acc[i][1], 0.f));
        o.z = sqrtf(fmaxf(sqr + sq[c + 2] - 2.f * acc[i][2], 0.f));
        o.w = sqrtf(fmaxf(sqr + sq[c + 3] - 2.f * acc[i][3], 0.f));
        *(float4*)(D + (size_t)r * N_NODES + c) = o;
    }
#undef D_STORE
#undef D_COMPUTE
}

// ---------------- kNN: 8 smallest per row (diag excluded), redux merge -------
__global__ void knn_kernel(const float* __restrict__ D, int* __restrict__ neigh) {
    int gw = (blockIdx.x * blockDim.x + threadIdx.x) >> 5;
    int lane = threadIdx.x & 31;
    if (gw >= N_NODES) return;
    const float* row = D + (size_t)gw * N_NODES;
    float val[8]; int idx[8];
#pragma unroll
    for (int r = 0; r < 8; r++) { val[r] = __int_as_float(0x7f800000); idx[r] = 0; }
    for (int j = lane; j < N_NODES; j += 32) {
        if (j == gw) continue;
        float v = row[j];
        if (v < val[7]) {
            val[7] = v; idx[7] = j;
#pragma unroll
            for (int p = 7; p > 0; p--) {
                if (val[p] < val[p - 1]) {
                    float tv = val[p]; val[p] = val[p - 1]; val[p - 1] = tv;
                    int   ti = idx[p]; idx[p] = idx[p - 1]; idx[p - 1] = ti;
                }
            }
        }
    }
    int ptr = 0;
#pragma unroll
    for (int r = 0; r < 8; r++) {
        unsigned vb = (ptr < 8) ? __float_as_uint(val[ptr]) : 0x7f800000u;
        unsigned vm = __reduce_min_sync(0xffffffffu, vb);
        unsigned mi = (ptr < 8 && vb == vm) ? (unsigned)idx[ptr] : 0x7fffffffu;
        unsigned im = __reduce_min_sync(0xffffffffu, mi);
        if (lane == 0) neigh[gw * KNB + r] = (int)im;
        if (ptr < 8 && vb == vm && (unsigned)idx[ptr] == im) ptr++;
    }
}

// ---------------- sequential k-means: 8 warps, 1 barrier/step ----------------
// thread t owns i = j*256 + t (j = 0..3). Every warp redundantly finalizes the
// previous centroid update and selects the cluster. BOTH cross-step shared
// structures are double-buffered by step parity:
//   red   : write buf step&1, read buf (step+1)&1 (= previous step's buffer)
//   Drow_sh: read buf step&1, rotate-write buf (step+1)&1
// -> no read/write conflict inside the single barrier epoch (this was the
//    deterministic R7/R8 corruption: same-epoch select-read vs rotate-write).
__global__ __launch_bounds__(256) void kmeans_kernel(
    const float* __restrict__ D, const int* __restrict__ perm,
    int* __restrict__ assign_out) {
    __shared__ float S[KC * N_NODES];       // 32KB, owner-thread only
    __shared__ float Drow_sh[2][N_NODES];   // 8KB, parity double-buffered
    __shared__ int   sperm[N_NODES];        // 4KB, read-only after init
    __shared__ u64   red[2][8];             // parity double-buffered
    const int t = threadIdx.x;
    const int lane = t & 31;
    const int wid = t >> 5;
    const float INF = __int_as_float(0x7f800000);
    const unsigned FULL = 0xffffffffu;

    for (int i = t; i < N_NODES; i += 256) sperm[i] = perm[i];
    __syncthreads();
    int mycent = (lane < KC) ? sperm[lane] : 0;   // replicated in every warp
    for (int c = 0; c < KC; c++) {
        const float* row = D + (size_t)sperm[c] * N_NODES;
#pragma unroll
        for (int j = 0; j < 4; j++)
            S[c * N_NODES + j * 256 + t] = row[j * 256 + t];
    }
    // membership nibbles: slot j (global i = j*256+t), value = cluster+1
    unsigned nib = 0u;
    for (int c = 0; c < KC; c++) {
        int p = sperm[c];
        if ((p & 255) == t) nib |= (unsigned)(c + 1) << ((p >> 8) * 4);
    }
    float cur[4];
    {
        const float* row = D + (size_t)sperm[KC] * N_NODES;
#pragma unroll
        for (int j = 0; j < 4; j++) {
            cur[j] = row[j * 256 + t];
            Drow_sh[0][j * 256 + t] = cur[j];
        }
    }
    int c_prev = -1;   // warp-uniform
    __syncthreads();

    for (int step = 0; step < NSTEPS; step++) {
        const int ni = sperm[KC + step];
        const int rb = step & 1;           // read buffer (Drow_sh + red write)
        const int wb = rb ^ 1;             // write buffer for next step's row
        // finalize previous step's centroid (redundant in all 8 warps)
        if (step > 0) {
            u64 rv = (lane < 8) ? red[wb][lane] : ~0ull;   // prev step's buffer
            unsigned hv = (unsigned)(rv >> 32);
            unsigned hm = __reduce_min_sync(FULL, hv);
            unsigned cand = (hv == hm) ? (unsigned)(rv & 0xffffffffull) : 0xffffffffu;
            unsigned newc = __reduce_min_sync(FULL, cand);
            if (lane == c_prev) mycent = (int)newc;
        }
        // select nearest centroid for ni (redundant; first-index tiebreak)
        unsigned cb = (lane < KC) ? __float_as_uint(Drow_sh[rb][mycent]) : 0x7f800000u;
        unsigned cm = __reduce_min_sync(FULL, cb);
        unsigned cmask = __ballot_sync(FULL, cb == cm);
        const int c = __ffs(cmask) - 1;
        c_prev = c;
        const unsigned tgt = (unsigned)(c + 1);
        // prefetch next node's D row (coalesced)
        float nxt[4];
        {
            const int nn = sperm[KC + ((step + 1 < NSTEPS) ? step + 1 : step)];
            const float* row = D + (size_t)nn * N_NODES;
#pragma unroll
            for (int j = 0; j < 4; j++) nxt[j] = row[j * 256 + t];
        }
        // S[c] += Drow; masked min (argmin of S over members == argmin of mean)
        float* Sc = S + c * N_NODES;
        float vv[4];
#pragma unroll
        for (int j = 0; j < 4; j++) {
            float s = Sc[j * 256 + t] + cur[j];
            Sc[j * 256 + t] = s;
            bool memb = (((nib >> (j * 4)) & 15u) == tgt) | ((j * 256 + t) == ni);
            vv[j] = memb ? s : INF;
        }
        float m0 = fminf(vv[0], vv[2]), m1 = fminf(vv[1], vv[3]);
        const float minv = fminf(m0, m1);
        unsigned msk = 0u;
#pragma unroll
        for (int j = 0; j < 4; j++) msk |= (vv[j] == minv) ? (1u << j) : 0u;
        const int besti = (__ffs(msk) - 1) * 256 + t;
        // per-warp argmin (value, then smallest global index)
        unsigned bb = __float_as_uint(minv);
        unsigned bm = __reduce_min_sync(FULL, bb);
        unsigned cand2 = (bb == bm) ? (unsigned)besti : 0xffffffffu;
        unsigned im = __reduce_min_sync(FULL, cand2);
        if (lane == 0) red[rb][wid] = ((u64)bm << 32) | im;
        // record assignment of ni
        if ((ni & 255) == t) nib |= tgt << ((ni >> 8) * 4);
        // rotate prefetched row into the OTHER buffer (read next step)
#pragma unroll
        for (int j = 0; j < 4; j++) {
            Drow_sh[wb][j * 256 + t] = nxt[j];
            cur[j] = nxt[j];
        }
        __syncthreads();   // red[rb] + Drow_sh[wb] visible for next step
    }
#pragma unroll
    for (int j = 0; j < 4; j++)
        assign_out[j * 256 + t] = (int)((nib >> (j * 4)) & 15u) - 1;
}

// ---------------- E[e] = sum_{v in neigh(e)} xf[v] ---------------------------
__global__ void agg_local_kernel(const float* __restrict__ xf, const int* __restrict__ neigh,
                                 float* __restrict__ E) {
    int e = blockIdx.x;
    int nb[KNB];
#pragma unroll
    for (int j = 0; j < KNB; j++) nb[j] = neigh[e * KNB + j];
    for (int c = threadIdx.x; c < C_DIM; c += 256) {
        float s = 0.f;
#pragma unroll
        for (int j = 0; j < KNB; j++) s += xf[(size_t)nb[j] * C_DIM + c];
        E[(size_t)e * C_DIM + c] = s;
    }
}

// ---------------- E[n+c] = sum_{assign[v]==c} xf[v] --------------------------
__global__ void agg_global_kernel(const float* __restrict__ xf, const int* __restrict__ assign_,
                                  float* __restrict__ E) {
    __shared__ int sa[N_NODES];
    int tid = threadIdx.x;
    for (int i = tid; i < N_NODES; i += 256) sa[i] = assign_[i];
    __syncthreads();
    int c = blockIdx.x;
    int col = blockIdx.y * 256 + tid;
    float s = 0.f;
    for (int i = 0; i < N_NODES; i++)
        if (sa[i] == c) s += xf[(size_t)i * C_DIM + col];
    E[(size_t)(N_NODES + c) * C_DIM + col] = s;
}

// ---------------- Y[v] = sum_{e: v in neigh(e)} X1[e] + X1[n+assign[v]] ------
__global__ void agg_out_kernel(const float* __restrict__ X1, const int* __restrict__ neigh,
                               const int* __restrict__ assign_, float* __restrict__ Y) {
    int v = blockIdx.x;
    __shared__ int list[N_NODES];
    __shared__ int cnt_s;
    int tid = threadIdx.x, lane = tid & 31, wid = tid >> 5;
    if (wid == 0) {
        int cnt = 0;
        for (int base = 0; base < N_NODES; base += 32) {
            int e = base + lane;
            const int4* p = (const int4*)(neigh + e * KNB);
            int4 q0 = p[0], q1 = p[1];
            bool m = (q0.x == v) | (q0.y == v) | (q0.z == v) | (q0.w == v) |
                     (q1.x == v) | (q1.y == v) | (q1.z == v) | (q1.w == v);
            unsigned msk = __ballot_sync(0xffffffffu, m);
            if (m) list[cnt + __popc(msk & ((1u << lane) - 1u))] = e;
            cnt += __popc(msk);
        }
        if (lane == 0) cnt_s = cnt;
    }
    __syncthreads();
    int cnt = cnt_s;
    int ge = N_NODES + assign_[v];
    float s[8];
#pragma unroll
    for (int w = 0; w < 8; w++) s[w] = X1[(size_t)ge * C_DIM + tid + w * 256];
    for (int t = 0; t < cnt; t++) {
        const float* xr = X1 + (size_t)list[t] * C_DIM;
#pragma unroll
        for (int w = 0; w < 8; w++) s[w] += xr[tid + w * 256];
    }
#pragma unroll
    for (int w = 0; w < 8; w++) Y[(size_t)v * C_DIM + tid + w * 256] = s[w];
}

// ---------------- host launcher ----------------------------------------------
extern "C" void kernel_launch(void* const* d_in, const int* in_sizes, int n_in,
                              void* d_out, int out_size) {
    const float* x0  = (const float*)d_in[0];
    const float* wfc = (const float*)d_in[1];
    const float* bfc = (const float*)d_in[2];
    const float* w1  = (const float*)d_in[3];
    const float* w2  = (const float*)d_in[4];
    float* out = (float*)d_out;

    float *xf, *sq, *D, *E, *X1, *Y;
    int *neigh, *perm, *assign_;
    cudaGetSymbolAddress((void**)&xf,      g_xf);
    cudaGetSymbolAddress((void**)&sq,      g_sq);
    cudaGetSymbolAddress((void**)&D,       g_D);
    cudaGetSymbolAddress((void**)&neigh,   g_neigh);
    cudaGetSymbolAddress((void**)&perm,    g_perm);
    cudaGetSymbolAddress((void**)&assign_, g_assign);
    cudaGetSymbolAddress((void**)&E,       g_E);
    cudaGetSymbolAddress((void**)&X1,      g_X1);
    cudaGetSymbolAddress((void**)&Y,       g_Y);

    const size_t dynsmem = (2 * AS_STAGE + 2 * BS_STAGE) * sizeof(float);  // 69632
    cudaFuncSetAttribute(mma_gemm_kernel,
                         cudaFuncAttributeMaxDynamicSharedMemorySize, (int)dynsmem);

    perm_kernel<<<1, 1024>>>(perm);
    sgemm_kernel<<<dim3(C_DIM / 128, N_NODES / 128), 256>>>(x0, wfc, bfc, xf,
                                                            N_NODES, C_DIM, C_DIM);
    rowsq_kernel<<<N_NODES, 256>>>(xf, sq);
    dist_kernel<<<dim3(N_NODES / 64, N_NODES / 128), 256>>>(xf, sq, D);
    knn_kernel<<<N_NODES / 8, 256>>>(D, neigh);
    kmeans_kernel<<<1, 256>>>(D, perm, assign_);
    agg_local_kernel<<<N_NODES, 256>>>(xf, neigh, E);
    agg_global_kernel<<<dim3(KC, C_DIM / 256), 256>>>(xf, assign_, E);
    mma_gemm_kernel<<<dim3(C_DIM / 128, E_PAD / 128), 256, dynsmem>>>(E, w1, X1);
    agg_out_kernel<<<N_NODES, 256>>>(X1, neigh, assign_, Y);
    mma_gemm_kernel<<<dim3(C_DIM / 128, N_NODES / 128), 256, dynsmem>>>(Y, w2, out);
}